// round 1
// baseline (speedup 1.0000x reference)
#include <cuda_runtime.h>
#include <math.h>

// Fixed problem shapes
#define B_   4
#define T_   2048
#define C_   768
#define H_   12
#define D_   64
#define M_   (B_ * T_)    // 8192
#define N1_  (3 * C_)     // 2304
#define BHD  (B_ * H_)    // 48

// ---------------- scratch (device globals; no allocation allowed) ----------------
__device__ float g_q[BHD * T_ * D_];    // [B,H,T,D]
__device__ float g_k[BHD * T_ * D_];
__device__ float g_v[BHD * T_ * D_];
__device__ float g_y[M_ * C_];          // attention output, [B,T,C]
__device__ float g_cosT[T_ * (D_ / 2)];
__device__ float g_sinT[T_ * (D_ / 2)];

// ---------------- RoPE tables (double precision, tiny one-shot kernel) -----------
__global__ void rope_tables_kernel() {
    int idx = blockIdx.x * blockDim.x + threadIdx.x;
    if (idx >= T_ * 32) return;
    int t = idx >> 5;
    int i = idx & 31;
    double inv = exp(-((double)i / 32.0) * log(10000.0));
    double ang = (double)t * inv;
    g_cosT[idx] = (float)cos(ang);
    g_sinT[idx] = (float)sin(ang);
}

// ---------------- RoPE apply (q and k in-place) -----------------------------------
__global__ void rope_apply_kernel() {
    int idx = blockIdx.x * blockDim.x + threadIdx.x;   // BHD*T_*32 threads
    if (idx >= BHD * T_ * 32) return;
    int i  = idx & 31;
    int t  = (idx >> 5) & (T_ - 1);
    int bh = idx >> 16;                                 // T_*32 = 65536
    float c = g_cosT[(t << 5) + i];
    float s = g_sinT[(t << 5) + i];
    size_t base = ((size_t)bh * T_ + t) * D_;
    float q1 = g_q[base + i], q2 = g_q[base + 32 + i];
    g_q[base + i]      =  q1 * c + q2 * s;
    g_q[base + 32 + i] = -q1 * s + q2 * c;
    float k1 = g_k[base + i], k2 = g_k[base + 32 + i];
    g_k[base + i]      =  k1 * c + k2 * s;
    g_k[base + 32 + i] = -k1 * s + k2 * c;
}

// ---------------- SGEMM 128x128x8, 256 threads, 8x8 per thread --------------------
// EPI==1: C = A@B + bias scattered into g_q/g_k/g_v head-major layout (QKV GEMM)
// EPI==0: A = g_y (device global), C = Cout[m*N+n] = A@B + bias     (output proj)
template <int N, int EPI>
__global__ __launch_bounds__(256) void sgemm_kernel(
    const float* __restrict__ Ain, const float* __restrict__ Bm,
    const float* __restrict__ bias, float* __restrict__ Cout)
{
    constexpr int K = C_;
    const float* A = (EPI == 0) ? (const float*)g_y : Ain;

    __shared__ float As[8][128];   // transposed A tile: As[k][m]
    __shared__ float Bs[8][128];   // Bs[k][n]

    const int tid = threadIdx.x;
    const int m0 = blockIdx.y * 128;
    const int n0 = blockIdx.x * 128;
    const int tr = tid >> 4;            // 0..15  (row group)
    const int tc = tid & 15;            // 0..15  (col group)
    const int arow = tid >> 1;          // 0..127
    const int acol = (tid & 1) * 4;     // 0 or 4
    const int brow = tid >> 5;          // 0..7
    const int bcol = (tid & 31) * 4;    // 0..124

    const float* Aptr = A  + (size_t)(m0 + arow) * K + acol;
    const float* Bptr = Bm + (size_t)brow * N + n0 + bcol;

    float acc[8][8];
#pragma unroll
    for (int i = 0; i < 8; i++)
#pragma unroll
        for (int j = 0; j < 8; j++) acc[i][j] = 0.f;

    for (int k0 = 0; k0 < K; k0 += 8) {
        float4 a4 = *(const float4*)(Aptr + k0);
        As[acol + 0][arow] = a4.x;
        As[acol + 1][arow] = a4.y;
        As[acol + 2][arow] = a4.z;
        As[acol + 3][arow] = a4.w;
        *(float4*)&Bs[brow][bcol] = *(const float4*)(Bptr + (size_t)k0 * N);
        __syncthreads();

#pragma unroll
        for (int k = 0; k < 8; k++) {
            float4 a0 = *(const float4*)&As[k][tr * 4];
            float4 a1 = *(const float4*)&As[k][64 + tr * 4];
            float4 b0 = *(const float4*)&Bs[k][tc * 4];
            float4 b1 = *(const float4*)&Bs[k][64 + tc * 4];
            float rm[8] = {a0.x, a0.y, a0.z, a0.w, a1.x, a1.y, a1.z, a1.w};
            float rn[8] = {b0.x, b0.y, b0.z, b0.w, b1.x, b1.y, b1.z, b1.w};
#pragma unroll
            for (int i = 0; i < 8; i++)
#pragma unroll
                for (int j = 0; j < 8; j++)
                    acc[i][j] += rm[i] * rn[j];
        }
        __syncthreads();
    }

    // epilogue
#pragma unroll
    for (int i = 0; i < 8; i++) {
        int m = m0 + ((i < 4) ? (tr * 4 + i) : (64 + tr * 4 + i - 4));
#pragma unroll
        for (int j = 0; j < 8; j++) {
            int n = n0 + ((j < 4) ? (tc * 4 + j) : (64 + tc * 4 + j - 4));
            float v = acc[i][j] + bias[n];
            if (EPI == 1) {
                int which = n / C_;                    // 0=q 1=k 2=v
                int rem = n - which * C_;
                int h = rem >> 6, d = rem & 63;
                int b = m >> 11, t = m & (T_ - 1);
                float* dst = (which == 0) ? g_q : ((which == 1) ? g_k : g_v);
                dst[(((size_t)(b * H_ + h)) * T_ + t) * D_ + d] = v;
            } else {
                Cout[(size_t)m * N + n] = v;
            }
        }
    }
}

// ---------------- Flash attention: 64q x 64k tiles, online softmax ----------------
// 256 threads: row = tid>>2 (query row in tile), g = tid&3 (4 lanes per row).
// Score phase: lane g computes keys j = 4*jj + g (conflict-free smem reads).
// PV phase: lane g owns output dims d = g*16 .. g*16+15 (float4 reads, 2-way conf).
// P tile reuses the K smem buffer (keeps static smem at 34.8 KB).
__global__ __launch_bounds__(256) void attn_kernel() {
    __shared__ float sK[64 * 68];
    __shared__ float sV[64 * 68];

    const int bh = blockIdx.y;
    const int qt = (int)gridDim.x - 1 - (int)blockIdx.x;  // longest tiles first
    const int b  = bh / H_;
    const int h  = bh - b * H_;
    const size_t hb = (size_t)bh * T_ * D_;
    const int tid = threadIdx.x;
    const int row = tid >> 2;
    const int g   = tid & 3;
    const int q_base = qt * 64;

    // stage Q tile through sK, pull own row into registers (pre-scaled)
    {
        const int r = tid >> 4, c = (tid & 15) * 4;
#pragma unroll
        for (int it = 0; it < 4; it++) {
            int rr = r + it * 16;
            *(float4*)(sK + rr * 68 + c) =
                *(const float4*)(g_q + hb + (size_t)(q_base + rr) * 64 + c);
        }
    }
    __syncthreads();
    float qreg[64];
#pragma unroll
    for (int d = 0; d < 64; d++) qreg[d] = sK[row * 68 + d] * 0.125f;

    float acc[16];
#pragma unroll
    for (int dd = 0; dd < 16; dd++) acc[dd] = 0.f;
    float mrow = -1e30f, lrow = 0.f;

    for (int kt = 0; kt <= qt; kt++) {
        const int k_base = kt * 64;
        __syncthreads();   // previous iteration's smem reads complete
        {
            const int r = tid >> 4, c = (tid & 15) * 4;
#pragma unroll
            for (int it = 0; it < 4; it++) {
                int rr = r + it * 16;
                *(float4*)(sK + rr * 68 + c) =
                    *(const float4*)(g_k + hb + (size_t)(k_base + rr) * 64 + c);
                *(float4*)(sV + rr * 68 + c) =
                    *(const float4*)(g_v + hb + (size_t)(k_base + rr) * 64 + c);
            }
        }
        __syncthreads();

        // scores for my 16 keys
        float s[16];
#pragma unroll
        for (int jj = 0; jj < 16; jj++) {
            const int j = jj * 4 + g;
            const float4* kr = (const float4*)(sK + j * 68);
            float sum = 0.f;
#pragma unroll
            for (int dw = 0; dw < 16; dw++) {
                float4 kv = kr[dw];
                sum += qreg[dw * 4 + 0] * kv.x + qreg[dw * 4 + 1] * kv.y
                     + qreg[dw * 4 + 2] * kv.z + qreg[dw * 4 + 3] * kv.w;
            }
            s[jj] = (k_base + j <= q_base + row) ? sum : -1e30f;
        }

        // online softmax (group of 4 lanes per row)
        float mloc = s[0];
#pragma unroll
        for (int jj = 1; jj < 16; jj++) mloc = fmaxf(mloc, s[jj]);
        mloc = fmaxf(mloc, __shfl_xor_sync(0xffffffffu, mloc, 1));
        mloc = fmaxf(mloc, __shfl_xor_sync(0xffffffffu, mloc, 2));
        const float mnew  = fmaxf(mrow, mloc);
        const float alpha = __expf(mrow - mnew);
        float lloc = 0.f;
#pragma unroll
        for (int jj = 0; jj < 16; jj++) {
            float p = __expf(s[jj] - mnew);
            s[jj] = p;
            lloc += p;
        }
        lloc += __shfl_xor_sync(0xffffffffu, lloc, 1);
        lloc += __shfl_xor_sync(0xffffffffu, lloc, 2);
        lrow = lrow * alpha + lloc;
        mrow = mnew;
#pragma unroll
        for (int dd = 0; dd < 16; dd++) acc[dd] *= alpha;

        // publish P into sK (everyone done reading K scores first)
        __syncthreads();
#pragma unroll
        for (int jj = 0; jj < 16; jj++) sK[row * 68 + jj * 4 + g] = s[jj];
        __syncthreads();

        // PV: acc[d] += sum_j P[row][j] * V[j][d],  d = g*16 .. g*16+15
#pragma unroll 2
        for (int j = 0; j < 64; j++) {
            float pj = sK[row * 68 + j];
            const float4* vr = (const float4*)(sV + j * 68 + g * 16);
#pragma unroll
            for (int dq = 0; dq < 4; dq++) {
                float4 vv = vr[dq];
                acc[dq * 4 + 0] += pj * vv.x;
                acc[dq * 4 + 1] += pj * vv.y;
                acc[dq * 4 + 2] += pj * vv.z;
                acc[dq * 4 + 3] += pj * vv.w;
            }
        }
    }

    const float inv = 1.f / lrow;
    float4* yo = (float4*)(g_y + ((size_t)(b * T_) + q_base + row) * C_ + h * 64 + g * 16);
#pragma unroll
    for (int dq = 0; dq < 4; dq++)
        yo[dq] = make_float4(acc[dq * 4 + 0] * inv, acc[dq * 4 + 1] * inv,
                             acc[dq * 4 + 2] * inv, acc[dq * 4 + 3] * inv);
}

// ---------------- launch ----------------------------------------------------------
extern "C" void kernel_launch(void* const* d_in, const int* in_sizes, int n_in,
                              void* d_out, int out_size) {
    (void)in_sizes; (void)n_in; (void)out_size;
    const float* x      = (const float*)d_in[0];
    const float* W_attn = (const float*)d_in[1];
    const float* b_attn = (const float*)d_in[2];
    const float* W_proj = (const float*)d_in[3];
    const float* b_proj = (const float*)d_in[4];
    float* out = (float*)d_out;

    rope_tables_kernel<<<(T_ * 32 + 255) / 256, 256>>>();
    sgemm_kernel<N1_, 1><<<dim3(N1_ / 128, M_ / 128), 256>>>(x, W_attn, b_attn, nullptr);
    rope_apply_kernel<<<(BHD * T_ * 32 + 255) / 256, 256>>>();
    attn_kernel<<<dim3(T_ / 64, BHD), 256>>>();
    sgemm_kernel<C_, 0><<<dim3(C_ / 128, M_ / 128), 256>>>(nullptr, W_proj, b_proj, out);
}

// round 2
// speedup vs baseline: 1.9459x; 1.9459x over previous
#include <cuda_runtime.h>
#include <math.h>

// Fixed problem shapes
#define B_   4
#define T_   2048
#define C_   768
#define H_   12
#define D_   64
#define M_   (B_ * T_)    // 8192
#define N1_  (3 * C_)     // 2304
#define BHD  (B_ * H_)    // 48

// ---------------- scratch (device globals; no allocation allowed) ----------------
__device__ float g_q[BHD * T_ * D_];    // [B,H,T,D]
__device__ float g_k[BHD * T_ * D_];
__device__ float g_v[BHD * T_ * D_];
__device__ float g_y[M_ * C_];          // attention output, [B,T,C]
__device__ float g_cosT[T_ * (D_ / 2)];
__device__ float g_sinT[T_ * (D_ / 2)];

// ---------------- RoPE tables (double precision, tiny one-shot kernel) -----------
__global__ void rope_tables_kernel() {
    int idx = blockIdx.x * blockDim.x + threadIdx.x;
    if (idx >= T_ * 32) return;
    int t = idx >> 5;
    int i = idx & 31;
    double inv = exp(-((double)i / 32.0) * log(10000.0));
    double ang = (double)t * inv;
    g_cosT[idx] = (float)cos(ang);
    g_sinT[idx] = (float)sin(ang);
}

// ---------------- RoPE apply (q and k in-place) -----------------------------------
__global__ void rope_apply_kernel() {
    int idx = blockIdx.x * blockDim.x + threadIdx.x;   // BHD*T_*32 threads
    if (idx >= BHD * T_ * 32) return;
    int i  = idx & 31;
    int t  = (idx >> 5) & (T_ - 1);
    int bh = idx >> 16;                                 // T_*32 = 65536
    float c = g_cosT[(t << 5) + i];
    float s = g_sinT[(t << 5) + i];
    size_t base = ((size_t)bh * T_ + t) * D_;
    float q1 = g_q[base + i], q2 = g_q[base + 32 + i];
    g_q[base + i]      =  q1 * c + q2 * s;
    g_q[base + 32 + i] = -q1 * s + q2 * c;
    float k1 = g_k[base + i], k2 = g_k[base + 32 + i];
    g_k[base + i]      =  k1 * c + k2 * s;
    g_k[base + 32 + i] = -k1 * s + k2 * c;
}

// ---------------- SGEMM 128x128x8, 256 threads, 8x8 per thread --------------------
template <int N, int EPI>
__global__ __launch_bounds__(256) void sgemm_kernel(
    const float* __restrict__ Ain, const float* __restrict__ Bm,
    const float* __restrict__ bias, float* __restrict__ Cout)
{
    constexpr int K = C_;
    const float* A = (EPI == 0) ? (const float*)g_y : Ain;

    __shared__ float As[8][128];   // transposed A tile: As[k][m]
    __shared__ float Bs[8][128];   // Bs[k][n]

    const int tid = threadIdx.x;
    const int m0 = blockIdx.y * 128;
    const int n0 = blockIdx.x * 128;
    const int tr = tid >> 4;
    const int tc = tid & 15;
    const int arow = tid >> 1;
    const int acol = (tid & 1) * 4;
    const int brow = tid >> 5;
    const int bcol = (tid & 31) * 4;

    const float* Aptr = A  + (size_t)(m0 + arow) * K + acol;
    const float* Bptr = Bm + (size_t)brow * N + n0 + bcol;

    float acc[8][8];
#pragma unroll
    for (int i = 0; i < 8; i++)
#pragma unroll
        for (int j = 0; j < 8; j++) acc[i][j] = 0.f;

    for (int k0 = 0; k0 < K; k0 += 8) {
        float4 a4 = *(const float4*)(Aptr + k0);
        As[acol + 0][arow] = a4.x;
        As[acol + 1][arow] = a4.y;
        As[acol + 2][arow] = a4.z;
        As[acol + 3][arow] = a4.w;
        *(float4*)&Bs[brow][bcol] = *(const float4*)(Bptr + (size_t)k0 * N);
        __syncthreads();

#pragma unroll
        for (int k = 0; k < 8; k++) {
            float4 a0 = *(const float4*)&As[k][tr * 4];
            float4 a1 = *(const float4*)&As[k][64 + tr * 4];
            float4 b0 = *(const float4*)&Bs[k][tc * 4];
            float4 b1 = *(const float4*)&Bs[k][64 + tc * 4];
            float rm[8] = {a0.x, a0.y, a0.z, a0.w, a1.x, a1.y, a1.z, a1.w};
            float rn[8] = {b0.x, b0.y, b0.z, b0.w, b1.x, b1.y, b1.z, b1.w};
#pragma unroll
            for (int i = 0; i < 8; i++)
#pragma unroll
                for (int j = 0; j < 8; j++)
                    acc[i][j] += rm[i] * rn[j];
        }
        __syncthreads();
    }

#pragma unroll
    for (int i = 0; i < 8; i++) {
        int m = m0 + ((i < 4) ? (tr * 4 + i) : (64 + tr * 4 + i - 4));
#pragma unroll
        for (int j = 0; j < 8; j++) {
            int n = n0 + ((j < 4) ? (tc * 4 + j) : (64 + tc * 4 + j - 4));
            float v = acc[i][j] + bias[n];
            if (EPI == 1) {
                int which = n / C_;
                int rem = n - which * C_;
                int h = rem >> 6, d = rem & 63;
                int b = m >> 11, t = m & (T_ - 1);
                float* dst = (which == 0) ? g_q : ((which == 1) ? g_k : g_v);
                dst[(((size_t)(b * H_ + h)) * T_ + t) * D_ + d] = v;
            } else {
                Cout[(size_t)m * N + n] = v;
            }
        }
    }
}

// ---------------- Flash attention v2: 128q x 128k block tiles ---------------------
// 256 threads. S = Q@K^T with 8x8 register micro-tiles (16x16 thread grid),
// online softmax with shfl reductions over the 16 threads sharing 8 q rows,
// P staged to smem transposed, PV with 8q x 4d micro-tiles.
// Smem (dynamic, 166KB): Qt[64][132], Kt[64][132], Vs[128][68], Pt[128][132].
#define QT_OFF 0
#define KT_OFF (64 * 132)
#define VS_OFF (2 * 64 * 132)
#define PT_OFF (2 * 64 * 132 + 128 * 68)
#define ATTN_SMEM_FLOATS (2 * 64 * 132 + 128 * 68 + 128 * 132)

__global__ __launch_bounds__(256, 1) void attn_kernel() {
    extern __shared__ float sm[];
    float* Qt = sm + QT_OFF;   // [d][q]  64x132
    float* Kt = sm + KT_OFF;   // [d][k]  64x132
    float* Vs = sm + VS_OFF;   // [k][d]  128x68
    float* Pt = sm + PT_OFF;   // [k][q]  128x132

    const int bh = blockIdx.y;
    const int qb = (int)gridDim.x - 1 - (int)blockIdx.x;   // longest first
    const int b  = bh / H_;
    const int h  = bh - b * H_;
    const size_t hb = (size_t)bh * T_ * D_;
    const int tid = threadIdx.x;
    const int tq  = tid >> 4;          // 0..15 -> q rows tq*8..tq*8+7
    const int tk  = tid & 15;          // 0..15 -> k cols tk*8..   / d cols tk*4..
    const int q0  = tq * 8;
    const int k0  = tk * 8;
    const int d0  = tk * 4;
    const int q_base = qb * 128;

    // ---- load Q tile transposed + pre-scaled ----
    {
        int j  = tid >> 4;
        int dd = (tid & 15) * 4;
#pragma unroll
        for (int it = 0; it < 8; it++, j += 16) {
            float4 v = *(const float4*)(g_q + hb + (size_t)(q_base + j) * 64 + dd);
            Qt[(dd + 0) * 132 + j] = v.x * 0.125f;
            Qt[(dd + 1) * 132 + j] = v.y * 0.125f;
            Qt[(dd + 2) * 132 + j] = v.z * 0.125f;
            Qt[(dd + 3) * 132 + j] = v.w * 0.125f;
        }
    }

    float accO[8][4];
#pragma unroll
    for (int i = 0; i < 8; i++)
#pragma unroll
        for (int c = 0; c < 4; c++) accO[i][c] = 0.f;
    float m[8], l[8];
#pragma unroll
    for (int i = 0; i < 8; i++) { m[i] = -1e30f; l[i] = 0.f; }

    for (int kt = 0; kt <= qb; kt++) {
        const int k_base = kt * 128;
        __syncthreads();   // prev PV reads done, Qt ready on first iter

        // ---- load K tile transposed, V tile straight ----
        {
            int j  = tid >> 4;
            int dd = (tid & 15) * 4;
#pragma unroll
            for (int it = 0; it < 8; it++, j += 16) {
                float4 kv = *(const float4*)(g_k + hb + (size_t)(k_base + j) * 64 + dd);
                Kt[(dd + 0) * 132 + j] = kv.x;
                Kt[(dd + 1) * 132 + j] = kv.y;
                Kt[(dd + 2) * 132 + j] = kv.z;
                Kt[(dd + 3) * 132 + j] = kv.w;
                *(float4*)(Vs + j * 68 + dd) =
                    *(const float4*)(g_v + hb + (size_t)(k_base + j) * 64 + dd);
            }
        }
        __syncthreads();

        // ---- S = Q @ K^T : 8x8 per thread ----
        float s[8][8];
#pragma unroll
        for (int i = 0; i < 8; i++)
#pragma unroll
            for (int j = 0; j < 8; j++) s[i][j] = 0.f;

#pragma unroll 4
        for (int d = 0; d < 64; d++) {
            float4 qa = *(const float4*)(Qt + d * 132 + q0);
            float4 qb4 = *(const float4*)(Qt + d * 132 + q0 + 4);
            float4 ka = *(const float4*)(Kt + d * 132 + k0);
            float4 kb = *(const float4*)(Kt + d * 132 + k0 + 4);
            float rq[8] = {qa.x, qa.y, qa.z, qa.w, qb4.x, qb4.y, qb4.z, qb4.w};
            float rk[8] = {ka.x, ka.y, ka.z, ka.w, kb.x, kb.y, kb.z, kb.w};
#pragma unroll
            for (int i = 0; i < 8; i++)
#pragma unroll
                for (int j = 0; j < 8; j++)
                    s[i][j] += rq[i] * rk[j];
        }

        // ---- causal mask on diagonal tile ----
        if (kt == qb) {
#pragma unroll
            for (int i = 0; i < 8; i++)
#pragma unroll
                for (int j = 0; j < 8; j++)
                    if (k0 + j > q0 + i) s[i][j] = -1e30f;
        }

        // ---- online softmax over the 16-thread row group ----
        float alpha[8];
#pragma unroll
        for (int i = 0; i < 8; i++) {
            float mx = s[i][0];
#pragma unroll
            for (int j = 1; j < 8; j++) mx = fmaxf(mx, s[i][j]);
            mx = fmaxf(mx, __shfl_xor_sync(0xffffffffu, mx, 1));
            mx = fmaxf(mx, __shfl_xor_sync(0xffffffffu, mx, 2));
            mx = fmaxf(mx, __shfl_xor_sync(0xffffffffu, mx, 4));
            mx = fmaxf(mx, __shfl_xor_sync(0xffffffffu, mx, 8));
            float mnew = fmaxf(m[i], mx);
            alpha[i] = __expf(m[i] - mnew);
            m[i] = mnew;
            float sum = 0.f;
#pragma unroll
            for (int j = 0; j < 8; j++) {
                float p = __expf(s[i][j] - mnew);
                s[i][j] = p;
                sum += p;
            }
            sum += __shfl_xor_sync(0xffffffffu, sum, 1);
            sum += __shfl_xor_sync(0xffffffffu, sum, 2);
            sum += __shfl_xor_sync(0xffffffffu, sum, 4);
            sum += __shfl_xor_sync(0xffffffffu, sum, 8);
            l[i] = l[i] * alpha[i] + sum;
#pragma unroll
            for (int c = 0; c < 4; c++) accO[i][c] *= alpha[i];
        }

        // ---- write P transposed: Pt[k][q] ----
#pragma unroll
        for (int j = 0; j < 8; j++) {
            float4 pa = make_float4(s[0][j], s[1][j], s[2][j], s[3][j]);
            float4 pb = make_float4(s[4][j], s[5][j], s[6][j], s[7][j]);
            *(float4*)(Pt + (k0 + j) * 132 + q0)     = pa;
            *(float4*)(Pt + (k0 + j) * 132 + q0 + 4) = pb;
        }
        __syncthreads();

        // ---- PV: accO[8q][4d] += P^T . V ----
#pragma unroll 4
        for (int j = 0; j < 128; j++) {
            float4 pa = *(const float4*)(Pt + j * 132 + q0);
            float4 pb = *(const float4*)(Pt + j * 132 + q0 + 4);
            float4 vv = *(const float4*)(Vs + j * 68 + d0);
            float rp[8] = {pa.x, pa.y, pa.z, pa.w, pb.x, pb.y, pb.z, pb.w};
#pragma unroll
            for (int i = 0; i < 8; i++) {
                accO[i][0] += rp[i] * vv.x;
                accO[i][1] += rp[i] * vv.y;
                accO[i][2] += rp[i] * vv.z;
                accO[i][3] += rp[i] * vv.w;
            }
        }
    }

    // ---- epilogue: y[b, q, h*64 + d] = accO / l ----
#pragma unroll
    for (int i = 0; i < 8; i++) {
        float inv = 1.f / l[i];
        float4 o = make_float4(accO[i][0] * inv, accO[i][1] * inv,
                               accO[i][2] * inv, accO[i][3] * inv);
        *(float4*)(g_y + ((size_t)(b * T_) + q_base + q0 + i) * C_ + h * 64 + d0) = o;
    }
}

// ---------------- launch ----------------------------------------------------------
extern "C" void kernel_launch(void* const* d_in, const int* in_sizes, int n_in,
                              void* d_out, int out_size) {
    (void)in_sizes; (void)n_in; (void)out_size;
    const float* x      = (const float*)d_in[0];
    const float* W_attn = (const float*)d_in[1];
    const float* b_attn = (const float*)d_in[2];
    const float* W_proj = (const float*)d_in[3];
    const float* b_proj = (const float*)d_in[4];
    float* out = (float*)d_out;

    static int smem_set = 0;
    if (!smem_set) {
        cudaFuncSetAttribute(attn_kernel, cudaFuncAttributeMaxDynamicSharedMemorySize,
                             ATTN_SMEM_FLOATS * 4);
        smem_set = 1;
    }

    rope_tables_kernel<<<(T_ * 32 + 255) / 256, 256>>>();
    sgemm_kernel<N1_, 1><<<dim3(N1_ / 128, M_ / 128), 256>>>(x, W_attn, b_attn, nullptr);
    rope_apply_kernel<<<(BHD * T_ * 32 + 255) / 256, 256>>>();
    attn_kernel<<<dim3(T_ / 128, BHD), 256, ATTN_SMEM_FLOATS * 4>>>();
    sgemm_kernel<C_, 0><<<dim3(C_ / 128, M_ / 128), 256>>>(nullptr, W_proj, b_proj, out);
}

// round 5
// speedup vs baseline: 2.5421x; 1.3064x over previous
#include <cuda_runtime.h>
#include <cuda_bf16.h>
#include <math.h>
#include <cstdint>

// Fixed problem shapes
#define B_   4
#define T_   2048
#define C_   768
#define H_   12
#define D_   64
#define M_   (B_ * T_)    // 8192
#define N1_  (3 * C_)     // 2304
#define BHD  (B_ * H_)    // 48

// ---------------- scratch (device globals; referenced ONLY in device code) --------
__device__ float g_q[BHD * T_ * D_];    // [B,H,T,D]
__device__ float g_k[BHD * T_ * D_];
__device__ float g_v[BHD * T_ * D_];
__device__ float g_y[M_ * C_];          // attention output, [B,T,C]
__device__ float g_cosT[T_ * (D_ / 2)];
__device__ float g_sinT[T_ * (D_ / 2)];

// bf16 hi/lo operand buffers for tensor-core GEMMs
__device__ __nv_bfloat16 g_xh[M_ * C_],  g_xl[M_ * C_];    // x split
__device__ __nv_bfloat16 g_yh[M_ * C_],  g_yl[M_ * C_];    // attn output split
__device__ __nv_bfloat16 g_wah[N1_ * C_], g_wal[N1_ * C_]; // W_attn^T [N][K]
__device__ __nv_bfloat16 g_wph[C_ * C_],  g_wpl[C_ * C_];  // W_proj^T [N][K]

// ---------------- helpers -----------------------------------------------------------
__device__ __forceinline__ uint32_t smem_u32(const void* p) {
    uint32_t a;
    asm("{ .reg .u64 t; cvta.to.shared.u64 t, %1; cvt.u32.u64 %0, t; }" : "=r"(a) : "l"(p));
    return a;
}
#define LDSM_X4(r, a)                                                           \
    asm volatile("ldmatrix.sync.aligned.m8n8.x4.shared.b16 {%0,%1,%2,%3},[%4];" \
        : "=r"((r)[0]), "=r"((r)[1]), "=r"((r)[2]), "=r"((r)[3]) : "r"(a))
#define MMA16816(d, a, b0, b1)                                                  \
    asm volatile("mma.sync.aligned.m16n8k16.row.col.f32.bf16.bf16.f32 "         \
        "{%0,%1,%2,%3},{%4,%5,%6,%7},{%8,%9},{%0,%1,%2,%3};"                    \
        : "+f"((d)[0]), "+f"((d)[1]), "+f"((d)[2]), "+f"((d)[3])                \
        : "r"((a)[0]), "r"((a)[1]), "r"((a)[2]), "r"((a)[3]), "r"(b0), "r"(b1))

// ---------------- RoPE tables ------------------------------------------------------
__global__ void rope_tables_kernel() {
    int idx = blockIdx.x * blockDim.x + threadIdx.x;
    if (idx >= T_ * 32) return;
    int t = idx >> 5;
    int i = idx & 31;
    double inv = exp(-((double)i / 32.0) * log(10000.0));
    double ang = (double)t * inv;
    g_cosT[idx] = (float)cos(ang);
    g_sinT[idx] = (float)sin(ang);
}

// ---------------- RoPE apply (q and k in-place) ------------------------------------
__global__ void rope_apply_kernel() {
    int idx = blockIdx.x * blockDim.x + threadIdx.x;
    if (idx >= BHD * T_ * 32) return;
    int i  = idx & 31;
    int t  = (idx >> 5) & (T_ - 1);
    int bh = idx >> 16;
    float c = g_cosT[(t << 5) + i];
    float s = g_sinT[(t << 5) + i];
    size_t base = ((size_t)bh * T_ + t) * D_;
    float q1 = g_q[base + i], q2 = g_q[base + 32 + i];
    g_q[base + i]      =  q1 * c + q2 * s;
    g_q[base + 32 + i] = -q1 * s + q2 * c;
    float k1 = g_k[base + i], k2 = g_k[base + 32 + i];
    g_k[base + i]      =  k1 * c + k2 * s;
    g_k[base + 32 + i] = -k1 * s + k2 * c;
}

// ---------------- fp32 -> bf16 hi/lo split (no transpose) --------------------------
// WHICH==0: src = external x (arg), dst g_xh/g_xl. WHICH==1: src = g_y, dst g_yh/g_yl.
template <int WHICH>
__global__ void convert_split_kernel(const float* __restrict__ xsrc) {
    const int n4 = M_ * C_ / 4;
    int i = blockIdx.x * blockDim.x + threadIdx.x;
    if (i >= n4) return;
    const float* src = (WHICH == 0) ? xsrc : (const float*)g_y;
    __nv_bfloat16* h = (WHICH == 0) ? g_xh : g_yh;
    __nv_bfloat16* l = (WHICH == 0) ? g_xl : g_yl;
    float4 v = ((const float4*)src)[i];
    float vv[4] = {v.x, v.y, v.z, v.w};
    uint32_t ph[2], pl[2];
#pragma unroll
    for (int p = 0; p < 2; p++) {
        __nv_bfloat16 h0 = __float2bfloat16(vv[p * 2]);
        __nv_bfloat16 h1 = __float2bfloat16(vv[p * 2 + 1]);
        __nv_bfloat16 l0 = __float2bfloat16(vv[p * 2] - __bfloat162float(h0));
        __nv_bfloat16 l1 = __float2bfloat16(vv[p * 2 + 1] - __bfloat162float(h1));
        ph[p] = (uint32_t)__bfloat16_as_ushort(h0) | ((uint32_t)__bfloat16_as_ushort(h1) << 16);
        pl[p] = (uint32_t)__bfloat16_as_ushort(l0) | ((uint32_t)__bfloat16_as_ushort(l1) << 16);
    }
    ((uint2*)h)[i] = make_uint2(ph[0], ph[1]);
    ((uint2*)l)[i] = make_uint2(pl[0], pl[1]);
}

// ---------------- W[K][N] -> W^T[N][K] with hi/lo split (tiled transpose) ----------
// WHICH==0: W_attn -> g_wah/g_wal (N=N1_). WHICH==1: W_proj -> g_wph/g_wpl (N=C_).
template <int WHICH>
__global__ void convert_wT_kernel(const float* __restrict__ W) {
    const int K = C_;
    const int N = (WHICH == 0) ? N1_ : C_;
    __nv_bfloat16* Th = (WHICH == 0) ? g_wah : g_wph;
    __nv_bfloat16* Tl = (WHICH == 0) ? g_wal : g_wpl;
    __shared__ float tile[32][33];
    int k0 = blockIdx.y * 32, n0 = blockIdx.x * 32;
    int tx = threadIdx.x, ty = threadIdx.y;
    for (int r = ty; r < 32; r += 8)
        tile[r][tx] = W[(size_t)(k0 + r) * N + n0 + tx];
    __syncthreads();
    for (int r = ty; r < 32; r += 8) {
        float v = tile[tx][r];
        __nv_bfloat16 h = __float2bfloat16(v);
        __nv_bfloat16 l = __float2bfloat16(v - __bfloat162float(h));
        size_t o = (size_t)(n0 + r) * K + k0 + tx;
        Th[o] = h;
        Tl[o] = l;
    }
}

// ---------------- mma.sync GEMM: D[128m,128n] = A[m,K].B^T[n,K] + bias -------------
// bf16 hi/lo 3-pass (AhBh + AhBl + AlBh), BK=32, cp.async double buffer.
// 256 threads = 8 warps in 4(m) x 2(n); warp tile 32x64 = 2x8 m16n8k16 atoms.
// EPI==1: A = g_xh/g_xl, B = g_wah/g_wal, scatter q/k/v head-major.
// EPI==0: A = g_yh/g_yl, B = g_wph/g_wpl, linear Cout[m*NT+n].
#define STAGE_B   40960
#define TILE_B    10240
#define GEMM_SMEM (2 * STAGE_B)

template <int NT, int EPI>
__global__ __launch_bounds__(256, 1) void tc_gemm_kernel(
    const float* __restrict__ bias, float* __restrict__ Cout)
{
    extern __shared__ __align__(128) char smem[];
    const uint32_t sb0 = smem_u32(smem);
    const int tid  = threadIdx.x;
    const int lane = tid & 31;
    const int warp = tid >> 5;
    const int m_w  = (warp >> 1) * 32;   // warp m origin in tile
    const int n_w  = (warp & 1) * 64;    // warp n origin in tile
    const int m0 = blockIdx.y * 128;
    const int n0 = blockIdx.x * 128;

    const __nv_bfloat16* srcs[4];
    if (EPI == 1) { srcs[0] = g_xh; srcs[1] = g_xl; srcs[2] = g_wah; srcs[3] = g_wal; }
    else          { srcs[0] = g_yh; srcs[1] = g_yl; srcs[2] = g_wph; srcs[3] = g_wpl; }

    auto load_chunk = [&](int kc, int st) {
        const uint32_t sbase = sb0 + (uint32_t)st * STAGE_B;
        const int k0 = kc * 32;
#pragma unroll
        for (int it = 0; it < 8; ++it) {
            int idx  = it * 256 + tid;
            int tile = idx >> 9;            // 0:Ah 1:Al 2:Bh 3:Bl
            int r    = (idx >> 2) & 127;
            int seg  = idx & 3;
            int rowbase = ((tile < 2) ? m0 : n0) + r;
            const void* g = srcs[tile] + (size_t)rowbase * C_ + k0 + seg * 8;
            uint32_t dst = sbase + (uint32_t)tile * TILE_B + (uint32_t)(r * 80 + seg * 16);
            asm volatile("cp.async.cg.shared.global [%0], [%1], 16;" :: "r"(dst), "l"(g));
        }
        asm volatile("cp.async.commit_group;" ::: "memory");
    };

    float acc[2][8][4];
#pragma unroll
    for (int i = 0; i < 2; i++)
#pragma unroll
        for (int j = 0; j < 8; j++)
#pragma unroll
            for (int r = 0; r < 4; r++) acc[i][j][r] = 0.f;

    load_chunk(0, 0);

    const int NCHUNK = C_ / 32;   // 24
    for (int c = 0; c < NCHUNK; ++c) {
        const int st = c & 1;
        if (c + 1 < NCHUNK) {
            load_chunk(c + 1, st ^ 1);
            asm volatile("cp.async.wait_group 1;" ::: "memory");
        } else {
            asm volatile("cp.async.wait_group 0;" ::: "memory");
        }
        __syncthreads();

        const uint32_t sA_h = sb0 + (uint32_t)st * STAGE_B;
        const uint32_t sA_l = sA_h + TILE_B;
        const uint32_t sB_h = sA_h + 2 * TILE_B;
        const uint32_t sB_l = sA_h + 3 * TILE_B;

        // A fragments for both k-steps (non-trans x4 on row-major [m][k])
        uint32_t aH[2][2][4], aL[2][2][4];   // [ks][m-atom]
#pragma unroll
        for (int ks = 0; ks < 2; ks++)
#pragma unroll
            for (int i = 0; i < 2; i++) {
                uint32_t ra = (uint32_t)((m_w + i * 16 + (lane & 15)) * 80 +
                                         ks * 32 + ((lane >> 4) & 1) * 16);
                LDSM_X4(aH[ks][i], sA_h + ra);
                LDSM_X4(aL[ks][i], sA_l + ra);
            }

#pragma unroll
        for (int j = 0; j < 8; j++) {
            // B fragments: non-trans x4 on [n][k] rows covers both k-steps
            uint32_t rb = (uint32_t)((n_w + j * 8 + (lane & 7)) * 80 +
                                     ((lane >> 3) & 3) * 16);
            uint32_t bH[4], bL[4];
            LDSM_X4(bH, sB_h + rb);
            LDSM_X4(bL, sB_l + rb);
#pragma unroll
            for (int ks = 0; ks < 2; ks++)
#pragma unroll
                for (int i = 0; i < 2; i++) {
                    MMA16816(acc[i][j], aH[ks][i], bH[ks * 2], bH[ks * 2 + 1]);
                    MMA16816(acc[i][j], aH[ks][i], bL[ks * 2], bL[ks * 2 + 1]);
                    MMA16816(acc[i][j], aL[ks][i], bH[ks * 2], bH[ks * 2 + 1]);
                }
        }
        __syncthreads();   // all reads of stage st done before it is refilled
    }

    // ---- epilogue: acc -> smem stage (bias added) -> coalesced gmem ----
    float* stg = (float*)smem;   // 128 x 132
#pragma unroll
    for (int i = 0; i < 2; i++) {
        int row = m_w + i * 16 + (lane >> 2);
#pragma unroll
        for (int j = 0; j < 8; j++) {
            int col = n_w + j * 8 + (lane & 3) * 2;
            float b0 = bias[n0 + col], b1 = bias[n0 + col + 1];
            stg[row * 132 + col]           = acc[i][j][0] + b0;
            stg[row * 132 + col + 1]       = acc[i][j][1] + b1;
            stg[(row + 8) * 132 + col]     = acc[i][j][2] + b0;
            stg[(row + 8) * 132 + col + 1] = acc[i][j][3] + b1;
        }
    }
    __syncthreads();

#pragma unroll
    for (int it = 0; it < 16; ++it) {
        int idx = it * 256 + tid;
        int ml = idx >> 5;
        int c4 = (idx & 31) * 4;
        float4 v = *(const float4*)(stg + ml * 132 + c4);
        if (EPI == 1) {
            int which = n0 / C_;
            int rem = n0 - which * C_ + c4;
            int h = rem >> 6, d = rem & 63;
            int m = m0 + ml;
            int b = m >> 11, t = m & (T_ - 1);
            float* base = (which == 0) ? g_q : ((which == 1) ? g_k : g_v);
            *(float4*)(base + (((size_t)(b * H_ + h)) * T_ + t) * 64 + d) = v;
        } else {
            *(float4*)(Cout + (size_t)(m0 + ml) * NT + n0 + c4) = v;
        }
    }
}

// ---------------- Flash attention v2: 128q x 128k block tiles (unchanged) ----------
#define QT_OFF 0
#define KT_OFF (64 * 132)
#define VS_OFF (2 * 64 * 132)
#define PT_OFF (2 * 64 * 132 + 128 * 68)
#define ATTN_SMEM_FLOATS (2 * 64 * 132 + 128 * 68 + 128 * 132)

__global__ __launch_bounds__(256, 1) void attn_kernel() {
    extern __shared__ float sm[];
    float* Qt = sm + QT_OFF;
    float* Kt = sm + KT_OFF;
    float* Vs = sm + VS_OFF;
    float* Pt = sm + PT_OFF;

    const int bh = blockIdx.y;
    const int qb = (int)gridDim.x - 1 - (int)blockIdx.x;
    const int b  = bh / H_;
    const int h  = bh - b * H_;
    const size_t hb = (size_t)bh * T_ * D_;
    const int tid = threadIdx.x;
    const int tq  = tid >> 4;
    const int tk  = tid & 15;
    const int q0  = tq * 8;
    const int k0  = tk * 8;
    const int d0  = tk * 4;
    const int q_base = qb * 128;

    {
        int j  = tid >> 4;
        int dd = (tid & 15) * 4;
#pragma unroll
        for (int it = 0; it < 8; it++, j += 16) {
            float4 v = *(const float4*)(g_q + hb + (size_t)(q_base + j) * 64 + dd);
            Qt[(dd + 0) * 132 + j] = v.x * 0.125f;
            Qt[(dd + 1) * 132 + j] = v.y * 0.125f;
            Qt[(dd + 2) * 132 + j] = v.z * 0.125f;
            Qt[(dd + 3) * 132 + j] = v.w * 0.125f;
        }
    }

    float accO[8][4];
#pragma unroll
    for (int i = 0; i < 8; i++)
#pragma unroll
        for (int c = 0; c < 4; c++) accO[i][c] = 0.f;
    float m[8], l[8];
#pragma unroll
    for (int i = 0; i < 8; i++) { m[i] = -1e30f; l[i] = 0.f; }

    for (int kt = 0; kt <= qb; kt++) {
        const int k_base = kt * 128;
        __syncthreads();
        {
            int j  = tid >> 4;
            int dd = (tid & 15) * 4;
#pragma unroll
            for (int it = 0; it < 8; it++, j += 16) {
                float4 kv = *(const float4*)(g_k + hb + (size_t)(k_base + j) * 64 + dd);
                Kt[(dd + 0) * 132 + j] = kv.x;
                Kt[(dd + 1) * 132 + j] = kv.y;
                Kt[(dd + 2) * 132 + j] = kv.z;
                Kt[(dd + 3) * 132 + j] = kv.w;
                *(float4*)(Vs + j * 68 + dd) =
                    *(const float4*)(g_v + hb + (size_t)(k_base + j) * 64 + dd);
            }
        }
        __syncthreads();

        float s[8][8];
#pragma unroll
        for (int i = 0; i < 8; i++)
#pragma unroll
            for (int j = 0; j < 8; j++) s[i][j] = 0.f;

#pragma unroll 4
        for (int d = 0; d < 64; d++) {
            float4 qa  = *(const float4*)(Qt + d * 132 + q0);
            float4 qb4 = *(const float4*)(Qt + d * 132 + q0 + 4);
            float4 ka  = *(const float4*)(Kt + d * 132 + k0);
            float4 kb  = *(const float4*)(Kt + d * 132 + k0 + 4);
            float rq[8] = {qa.x, qa.y, qa.z, qa.w, qb4.x, qb4.y, qb4.z, qb4.w};
            float rk[8] = {ka.x, ka.y, ka.z, ka.w, kb.x, kb.y, kb.z, kb.w};
#pragma unroll
            for (int i = 0; i < 8; i++)
#pragma unroll
                for (int j = 0; j < 8; j++)
                    s[i][j] += rq[i] * rk[j];
        }

        if (kt == qb) {
#pragma unroll
            for (int i = 0; i < 8; i++)
#pragma unroll
                for (int j = 0; j < 8; j++)
                    if (k0 + j > q0 + i) s[i][j] = -1e30f;
        }

        float alpha[8];
#pragma unroll
        for (int i = 0; i < 8; i++) {
            float mx = s[i][0];
#pragma unroll
            for (int j = 1; j < 8; j++) mx = fmaxf(mx, s[i][j]);
            mx = fmaxf(mx, __shfl_xor_sync(0xffffffffu, mx, 1));
            mx = fmaxf(mx, __shfl_xor_sync(0xffffffffu, mx, 2));
            mx = fmaxf(mx, __shfl_xor_sync(0xffffffffu, mx, 4));
            mx = fmaxf(mx, __shfl_xor_sync(0xffffffffu, mx, 8));
            float mnew = fmaxf(m[i], mx);
            alpha[i] = __expf(m[i] - mnew);
            m[i] = mnew;
            float sum = 0.f;
#pragma unroll
            for (int j = 0; j < 8; j++) {
                float p = __expf(s[i][j] - mnew);
                s[i][j] = p;
                sum += p;
            }
            sum += __shfl_xor_sync(0xffffffffu, sum, 1);
            sum += __shfl_xor_sync(0xffffffffu, sum, 2);
            sum += __shfl_xor_sync(0xffffffffu, sum, 4);
            sum += __shfl_xor_sync(0xffffffffu, sum, 8);
            l[i] = l[i] * alpha[i] + sum;
#pragma unroll
            for (int c = 0; c < 4; c++) accO[i][c] *= alpha[i];
        }

#pragma unroll
        for (int j = 0; j < 8; j++) {
            float4 pa = make_float4(s[0][j], s[1][j], s[2][j], s[3][j]);
            float4 pb = make_float4(s[4][j], s[5][j], s[6][j], s[7][j]);
            *(float4*)(Pt + (k0 + j) * 132 + q0)     = pa;
            *(float4*)(Pt + (k0 + j) * 132 + q0 + 4) = pb;
        }
        __syncthreads();

#pragma unroll 4
        for (int j = 0; j < 128; j++) {
            float4 pa = *(const float4*)(Pt + j * 132 + q0);
            float4 pb = *(const float4*)(Pt + j * 132 + q0 + 4);
            float4 vv = *(const float4*)(Vs + j * 68 + d0);
            float rp[8] = {pa.x, pa.y, pa.z, pa.w, pb.x, pb.y, pb.z, pb.w};
#pragma unroll
            for (int i = 0; i < 8; i++) {
                accO[i][0] += rp[i] * vv.x;
                accO[i][1] += rp[i] * vv.y;
                accO[i][2] += rp[i] * vv.z;
                accO[i][3] += rp[i] * vv.w;
            }
        }
    }

#pragma unroll
    for (int i = 0; i < 8; i++) {
        float inv = 1.f / l[i];
        float4 o = make_float4(accO[i][0] * inv, accO[i][1] * inv,
                               accO[i][2] * inv, accO[i][3] * inv);
        *(float4*)(g_y + ((size_t)(b * T_) + q_base + q0 + i) * C_ + h * 64 + d0) = o;
    }
}

// ---------------- launch ------------------------------------------------------------
extern "C" void kernel_launch(void* const* d_in, const int* in_sizes, int n_in,
                              void* d_out, int out_size) {
    (void)in_sizes; (void)n_in; (void)out_size;
    const float* x      = (const float*)d_in[0];
    const float* W_attn = (const float*)d_in[1];
    const float* b_attn = (const float*)d_in[2];
    const float* W_proj = (const float*)d_in[3];
    const float* b_proj = (const float*)d_in[4];
    float* out = (float*)d_out;

    cudaFuncSetAttribute(attn_kernel, cudaFuncAttributeMaxDynamicSharedMemorySize,
                         ATTN_SMEM_FLOATS * 4);
    cudaFuncSetAttribute(tc_gemm_kernel<N1_, 1>,
                         cudaFuncAttributeMaxDynamicSharedMemorySize, GEMM_SMEM);
    cudaFuncSetAttribute(tc_gemm_kernel<C_, 0>,
                         cudaFuncAttributeMaxDynamicSharedMemorySize, GEMM_SMEM);

    rope_tables_kernel<<<(T_ * 32 + 255) / 256, 256>>>();
    convert_split_kernel<0><<<(M_ * C_ / 4 + 255) / 256, 256>>>(x);
    convert_wT_kernel<0><<<dim3(N1_ / 32, C_ / 32), dim3(32, 8)>>>(W_attn);
    convert_wT_kernel<1><<<dim3(C_ / 32, C_ / 32), dim3(32, 8)>>>(W_proj);

    tc_gemm_kernel<N1_, 1><<<dim3(N1_ / 128, M_ / 128), 256, GEMM_SMEM>>>(b_attn, nullptr);

    rope_apply_kernel<<<(BHD * T_ * 32 + 255) / 256, 256>>>();
    attn_kernel<<<dim3(T_ / 128, BHD), 256, ATTN_SMEM_FLOATS * 4>>>();

    convert_split_kernel<1><<<(M_ * C_ / 4 + 255) / 256, 256>>>(nullptr);
    tc_gemm_kernel<C_, 0><<<dim3(C_ / 128, M_ / 128), 256, GEMM_SMEM>>>(b_proj, out);
}

// round 6
// speedup vs baseline: 4.2898x; 1.6875x over previous
#include <cuda_runtime.h>
#include <cuda_bf16.h>
#include <math.h>
#include <cstdint>

// Fixed problem shapes
#define B_   4
#define T_   2048
#define C_   768
#define H_   12
#define D_   64
#define M_   (B_ * T_)    // 8192
#define N1_  (3 * C_)     // 2304
#define BHD  (B_ * H_)    // 48

// ---------------- scratch (device globals; referenced ONLY in device code) --------
__device__ float g_q[BHD * T_ * D_];    // fp32 q (pre-rope), [B,H,T,D]
__device__ float g_k[BHD * T_ * D_];
__device__ float g_v[BHD * T_ * D_];
__device__ float g_cosT[T_ * (D_ / 2)];
__device__ float g_sinT[T_ * (D_ / 2)];

// bf16 hi/lo operand buffers
__device__ __nv_bfloat16 g_xh[M_ * C_],  g_xl[M_ * C_];      // x split
__device__ __nv_bfloat16 g_yh[M_ * C_],  g_yl[M_ * C_];      // attn out split
__device__ __nv_bfloat16 g_wah[N1_ * C_], g_wal[N1_ * C_];   // W_attn^T [N][K]
__device__ __nv_bfloat16 g_wph[C_ * C_],  g_wpl[C_ * C_];    // W_proj^T [N][K]
__device__ __nv_bfloat16 g_qh[BHD * T_ * D_], g_ql[BHD * T_ * D_];  // roped q (scaled)
__device__ __nv_bfloat16 g_kh[BHD * T_ * D_], g_kl[BHD * T_ * D_];  // roped k
__device__ __nv_bfloat16 g_vth[BHD * D_ * T_], g_vtl[BHD * D_ * T_]; // V^T [B,H,D,T]

// ---------------- helpers -----------------------------------------------------------
__device__ __forceinline__ uint32_t smem_u32(const void* p) {
    uint32_t a;
    asm("{ .reg .u64 t; cvta.to.shared.u64 t, %1; cvt.u32.u64 %0, t; }" : "=r"(a) : "l"(p));
    return a;
}
#define LDSM_X4(r, a)                                                           \
    asm volatile("ldmatrix.sync.aligned.m8n8.x4.shared.b16 {%0,%1,%2,%3},[%4];" \
        : "=r"((r)[0]), "=r"((r)[1]), "=r"((r)[2]), "=r"((r)[3]) : "r"(a))
#define MMA16816(d, a, b0, b1)                                                  \
    asm volatile("mma.sync.aligned.m16n8k16.row.col.f32.bf16.bf16.f32 "         \
        "{%0,%1,%2,%3},{%4,%5,%6,%7},{%8,%9},{%0,%1,%2,%3};"                    \
        : "+f"((d)[0]), "+f"((d)[1]), "+f"((d)[2]), "+f"((d)[3])                \
        : "r"((a)[0]), "r"((a)[1]), "r"((a)[2]), "r"((a)[3]), "r"(b0), "r"(b1))
#define CP16(dst, src) \
    asm volatile("cp.async.cg.shared.global [%0], [%1], 16;" :: "r"(dst), "l"(src))

__device__ __forceinline__ uint32_t bf2(float a, float b) {
    __nv_bfloat162 t = __floats2bfloat162_rn(a, b);
    return *(uint32_t*)&t;
}
__device__ __forceinline__ float bflo(float v) {   // residual after bf16 round
    return v - __bfloat162float(__float2bfloat16(v));
}

// ---------------- RoPE tables ------------------------------------------------------
__global__ void rope_tables_kernel() {
    int idx = blockIdx.x * blockDim.x + threadIdx.x;
    if (idx >= T_ * 32) return;
    int t = idx >> 5;
    int i = idx & 31;
    double inv = exp(-((double)i / 32.0) * log(10000.0));
    double ang = (double)t * inv;
    g_cosT[idx] = (float)cos(ang);
    g_sinT[idx] = (float)sin(ang);
}

// ---------------- RoPE apply: fp32 q/k -> roped bf16 hi/lo (q scaled 1/8) ---------
__global__ void rope_apply_kernel() {
    int idx = blockIdx.x * blockDim.x + threadIdx.x;
    if (idx >= BHD * T_ * 32) return;
    int i  = idx & 31;
    int t  = (idx >> 5) & (T_ - 1);
    int bh = idx >> 16;
    float c = g_cosT[(t << 5) + i];
    float s = g_sinT[(t << 5) + i];
    size_t base = ((size_t)bh * T_ + t) * D_;
    float q1 = g_q[base + i], q2 = g_q[base + 32 + i];
    float qa = (q1 * c + q2 * s) * 0.125f;
    float qb = (-q1 * s + q2 * c) * 0.125f;
    g_qh[base + i]      = __float2bfloat16(qa);
    g_ql[base + i]      = __float2bfloat16(bflo(qa));
    g_qh[base + 32 + i] = __float2bfloat16(qb);
    g_ql[base + 32 + i] = __float2bfloat16(bflo(qb));
    float k1 = g_k[base + i], k2 = g_k[base + 32 + i];
    float ka = k1 * c + k2 * s;
    float kb = -k1 * s + k2 * c;
    g_kh[base + i]      = __float2bfloat16(ka);
    g_kl[base + i]      = __float2bfloat16(bflo(ka));
    g_kh[base + 32 + i] = __float2bfloat16(kb);
    g_kl[base + 32 + i] = __float2bfloat16(bflo(kb));
}

// ---------------- V transpose: g_v [BH][T][D] fp32 -> [BH][D][T] bf16 hi/lo --------
__global__ void transpose_v_kernel() {
    __shared__ float tile[32][33];
    int bh = blockIdx.z;
    int t0 = blockIdx.x * 32;
    int d0 = blockIdx.y * 32;
    int tx = threadIdx.x, ty = threadIdx.y;
    size_t base = (size_t)bh * T_ * D_;
    for (int r = ty; r < 32; r += 8)
        tile[r][tx] = g_v[base + (size_t)(t0 + r) * D_ + d0 + tx];
    __syncthreads();
    for (int r = ty; r < 32; r += 8) {
        float v = tile[tx][r];
        size_t o = base + (size_t)(d0 + r) * T_ + t0 + tx;
        g_vth[o] = __float2bfloat16(v);
        g_vtl[o] = __float2bfloat16(bflo(v));
    }
}

// ---------------- fp32 -> bf16 hi/lo split of x -------------------------------------
__global__ void convert_split_kernel(const float* __restrict__ src) {
    const int n4 = M_ * C_ / 4;
    int i = blockIdx.x * blockDim.x + threadIdx.x;
    if (i >= n4) return;
    float4 v = ((const float4*)src)[i];
    float vv[4] = {v.x, v.y, v.z, v.w};
    uint32_t ph[2], pl[2];
#pragma unroll
    for (int p = 0; p < 2; p++) {
        ph[p] = bf2(vv[p * 2], vv[p * 2 + 1]);
        pl[p] = bf2(bflo(vv[p * 2]), bflo(vv[p * 2 + 1]));
    }
    ((uint2*)g_xh)[i] = make_uint2(ph[0], ph[1]);
    ((uint2*)g_xl)[i] = make_uint2(pl[0], pl[1]);
}

// ---------------- W[K][N] -> W^T[N][K] with hi/lo split -----------------------------
template <int WHICH>
__global__ void convert_wT_kernel(const float* __restrict__ W) {
    const int K = C_;
    const int N = (WHICH == 0) ? N1_ : C_;
    __nv_bfloat16* Th = (WHICH == 0) ? g_wah : g_wph;
    __nv_bfloat16* Tl = (WHICH == 0) ? g_wal : g_wpl;
    __shared__ float tile[32][33];
    int k0 = blockIdx.y * 32, n0 = blockIdx.x * 32;
    int tx = threadIdx.x, ty = threadIdx.y;
    for (int r = ty; r < 32; r += 8)
        tile[r][tx] = W[(size_t)(k0 + r) * N + n0 + tx];
    __syncthreads();
    for (int r = ty; r < 32; r += 8) {
        float v = tile[tx][r];
        size_t o = (size_t)(n0 + r) * K + k0 + tx;
        Th[o] = __float2bfloat16(v);
        Tl[o] = __float2bfloat16(bflo(v));
    }
}

// ---------------- mma.sync GEMM (unchanged from round 5) ---------------------------
#define STAGE_B   40960
#define TILE_B    10240
#define GEMM_SMEM (2 * STAGE_B)

template <int NT, int EPI>
__global__ __launch_bounds__(256, 1) void tc_gemm_kernel(
    const float* __restrict__ bias, float* __restrict__ Cout)
{
    extern __shared__ __align__(128) char smem[];
    const uint32_t sb0 = smem_u32(smem);
    const int tid  = threadIdx.x;
    const int lane = tid & 31;
    const int warp = tid >> 5;
    const int m_w  = (warp >> 1) * 32;
    const int n_w  = (warp & 1) * 64;
    const int m0 = blockIdx.y * 128;
    const int n0 = blockIdx.x * 128;

    const __nv_bfloat16* srcs[4];
    if (EPI == 1) { srcs[0] = g_xh; srcs[1] = g_xl; srcs[2] = g_wah; srcs[3] = g_wal; }
    else          { srcs[0] = g_yh; srcs[1] = g_yl; srcs[2] = g_wph; srcs[3] = g_wpl; }

    auto load_chunk = [&](int kc, int st) {
        const uint32_t sbase = sb0 + (uint32_t)st * STAGE_B;
        const int k0 = kc * 32;
#pragma unroll
        for (int it = 0; it < 8; ++it) {
            int idx  = it * 256 + tid;
            int tile = idx >> 9;
            int r    = (idx >> 2) & 127;
            int seg  = idx & 3;
            int rowbase = ((tile < 2) ? m0 : n0) + r;
            const void* g = srcs[tile] + (size_t)rowbase * C_ + k0 + seg * 8;
            uint32_t dst = sbase + (uint32_t)tile * TILE_B + (uint32_t)(r * 80 + seg * 16);
            CP16(dst, g);
        }
        asm volatile("cp.async.commit_group;" ::: "memory");
    };

    float acc[2][8][4];
#pragma unroll
    for (int i = 0; i < 2; i++)
#pragma unroll
        for (int j = 0; j < 8; j++)
#pragma unroll
            for (int r = 0; r < 4; r++) acc[i][j][r] = 0.f;

    load_chunk(0, 0);
    const int NCHUNK = C_ / 32;
    for (int c = 0; c < NCHUNK; ++c) {
        const int st = c & 1;
        if (c + 1 < NCHUNK) {
            load_chunk(c + 1, st ^ 1);
            asm volatile("cp.async.wait_group 1;" ::: "memory");
        } else {
            asm volatile("cp.async.wait_group 0;" ::: "memory");
        }
        __syncthreads();

        const uint32_t sA_h = sb0 + (uint32_t)st * STAGE_B;
        const uint32_t sA_l = sA_h + TILE_B;
        const uint32_t sB_h = sA_h + 2 * TILE_B;
        const uint32_t sB_l = sA_h + 3 * TILE_B;

        uint32_t aH[2][2][4], aL[2][2][4];
#pragma unroll
        for (int ks = 0; ks < 2; ks++)
#pragma unroll
            for (int i = 0; i < 2; i++) {
                uint32_t ra = (uint32_t)((m_w + i * 16 + (lane & 15)) * 80 +
                                         ks * 32 + ((lane >> 4) & 1) * 16);
                LDSM_X4(aH[ks][i], sA_h + ra);
                LDSM_X4(aL[ks][i], sA_l + ra);
            }
#pragma unroll
        for (int j = 0; j < 8; j++) {
            uint32_t rb = (uint32_t)((n_w + j * 8 + (lane & 7)) * 80 +
                                     ((lane >> 3) & 3) * 16);
            uint32_t bH[4], bL[4];
            LDSM_X4(bH, sB_h + rb);
            LDSM_X4(bL, sB_l + rb);
#pragma unroll
            for (int ks = 0; ks < 2; ks++)
#pragma unroll
                for (int i = 0; i < 2; i++) {
                    MMA16816(acc[i][j], aH[ks][i], bH[ks * 2], bH[ks * 2 + 1]);
                    MMA16816(acc[i][j], aH[ks][i], bL[ks * 2], bL[ks * 2 + 1]);
                    MMA16816(acc[i][j], aL[ks][i], bH[ks * 2], bH[ks * 2 + 1]);
                }
        }
        __syncthreads();
    }

    float* stg = (float*)smem;
#pragma unroll
    for (int i = 0; i < 2; i++) {
        int row = m_w + i * 16 + (lane >> 2);
#pragma unroll
        for (int j = 0; j < 8; j++) {
            int col = n_w + j * 8 + (lane & 3) * 2;
            float b0 = bias[n0 + col], b1 = bias[n0 + col + 1];
            stg[row * 132 + col]           = acc[i][j][0] + b0;
            stg[row * 132 + col + 1]       = acc[i][j][1] + b1;
            stg[(row + 8) * 132 + col]     = acc[i][j][2] + b0;
            stg[(row + 8) * 132 + col + 1] = acc[i][j][3] + b1;
        }
    }
    __syncthreads();
#pragma unroll
    for (int it = 0; it < 16; ++it) {
        int idx = it * 256 + tid;
        int ml = idx >> 5;
        int c4 = (idx & 31) * 4;
        float4 v = *(const float4*)(stg + ml * 132 + c4);
        if (EPI == 1) {
            int which = n0 / C_;
            int rem = n0 - which * C_ + c4;
            int h = rem >> 6, d = rem & 63;
            int m = m0 + ml;
            int b = m >> 11, t = m & (T_ - 1);
            float* base = (which == 0) ? g_q : ((which == 1) ? g_k : g_v);
            *(float4*)(base + (((size_t)(b * H_ + h)) * T_ + t) * 64 + d) = v;
        } else {
            *(float4*)(Cout + (size_t)(m0 + ml) * NT + n0 + c4) = v;
        }
    }
}

// ---------------- Tensor-core flash attention ---------------------------------------
// CTA = 128 q rows of one head; 8 warps, warp owns 16 q rows x full 128-k tile.
// QK^T: bf16 hi/lo 3-pass. Online softmax on acc frags (quad shfl). PV: P split
// to bf16 hi/lo in-register (FA2 acc->A-frag identity), V^T bf16 hi/lo 3-pass.
#define KSTG 18432                      // 128 rows * 144B
#define VSTG 17408                      // 64 rows * 272B
#define STG_BYTES (2 * KSTG + 2 * VSTG) // 71680
#define ATTN_SMEM (2 * STG_BYTES)       // 143360

__global__ __launch_bounds__(256, 1) void attn_mma_kernel() {
    extern __shared__ __align__(128) char sm[];
    const uint32_t sb = smem_u32(sm);
    const int tid  = threadIdx.x;
    const int lane = tid & 31;
    const int w    = tid >> 5;
    const int bh   = blockIdx.y;
    const int qb   = (int)gridDim.x - 1 - (int)blockIdx.x;   // longest first
    const int b    = bh / H_;
    const int h    = bh - b * H_;
    const size_t hb = (size_t)bh * T_ * D_;
    const int qbase = qb * 128;
    const int r0 = lane >> 2;          // quad row
    const int c2 = (lane & 3) * 2;     // quad col pair
    const int row_a = qbase + w * 16 + r0;   // this thread's first q row (global)

    // ---- Q A-fragments by direct 4B global loads (pairs are d-contiguous) ----
    uint32_t qfh[4][4], qfl[4][4];
#pragma unroll
    for (int ks = 0; ks < 4; ks++) {
        int d = ks * 16 + c2;
        size_t o0 = hb + (size_t)row_a * 64 + d;
        size_t o1 = hb + (size_t)(row_a + 8) * 64 + d;
        qfh[ks][0] = *(const uint32_t*)(g_qh + o0);
        qfh[ks][1] = *(const uint32_t*)(g_qh + o1);
        qfh[ks][2] = *(const uint32_t*)(g_qh + o0 + 8);
        qfh[ks][3] = *(const uint32_t*)(g_qh + o1 + 8);
        qfl[ks][0] = *(const uint32_t*)(g_ql + o0);
        qfl[ks][1] = *(const uint32_t*)(g_ql + o1);
        qfl[ks][2] = *(const uint32_t*)(g_ql + o0 + 8);
        qfl[ks][3] = *(const uint32_t*)(g_ql + o1 + 8);
    }

    const __nv_bfloat16* kh = g_kh + hb;
    const __nv_bfloat16* kl = g_kl + hb;
    const __nv_bfloat16* vh = g_vth + hb;
    const __nv_bfloat16* vl = g_vtl + hb;

    auto load_stage = [&](int kt, int st) {
        const uint32_t sbase = sb + (uint32_t)st * STG_BYTES;
        const int kbase = kt * 128;
#pragma unroll
        for (int it = 0; it < 8; ++it) {            // K tiles (hi, lo)
            int idx = it * 256 + tid;
            int tile = idx >> 10;
            int r    = (idx >> 3) & 127;
            int seg  = idx & 7;
            const void* g = (tile ? kl : kh) + (size_t)(kbase + r) * 64 + seg * 8;
            CP16(sbase + (uint32_t)(tile * KSTG + r * 144 + seg * 16), g);
        }
#pragma unroll
        for (int it = 0; it < 8; ++it) {            // V^T tiles (hi, lo)
            int idx = it * 256 + tid;
            int tile = idx >> 10;
            int r    = (idx >> 4) & 63;
            int seg  = idx & 15;
            const void* g = (tile ? vl : vh) + (size_t)r * T_ + kbase + seg * 8;
            CP16(sbase + (uint32_t)(2 * KSTG + tile * VSTG + r * 272 + seg * 16), g);
        }
        asm volatile("cp.async.commit_group;" ::: "memory");
    };

    float oacc[8][4];
#pragma unroll
    for (int jd = 0; jd < 8; jd++)
#pragma unroll
        for (int e = 0; e < 4; e++) oacc[jd][e] = 0.f;
    float m0 = -1e30f, m1 = -1e30f, l0 = 0.f, l1 = 0.f;

    load_stage(0, 0);

    for (int kt = 0; kt <= qb; kt++) {
        const int st = kt & 1;
        if (kt < qb) {
            load_stage(kt + 1, st ^ 1);
            asm volatile("cp.async.wait_group 1;" ::: "memory");
        } else {
            asm volatile("cp.async.wait_group 0;" ::: "memory");
        }
        __syncthreads();

        const uint32_t kb = sb + (uint32_t)st * STG_BYTES;

        // ---- S = Q K^T (3-pass hi/lo), 16 n8 acc tiles ----
        float sacc[16][4];
#pragma unroll
        for (int j = 0; j < 16; j++)
#pragma unroll
            for (int e = 0; e < 4; e++) sacc[j][e] = 0.f;

#pragma unroll
        for (int j = 0; j < 16; j++) {
            uint32_t rbase = kb + (uint32_t)((j * 8 + (lane & 7)) * 144 +
                                             ((lane >> 3) & 3) * 16);
#pragma unroll
            for (int half = 0; half < 2; half++) {
                uint32_t bH[4], bL[4];
                LDSM_X4(bH, rbase + half * 64);
                LDSM_X4(bL, rbase + KSTG + half * 64);
#pragma unroll
                for (int ki = 0; ki < 2; ki++) {
                    int ks = half * 2 + ki;
                    MMA16816(sacc[j], qfh[ks], bH[ki * 2], bH[ki * 2 + 1]);
                    MMA16816(sacc[j], qfh[ks], bL[ki * 2], bL[ki * 2 + 1]);
                    MMA16816(sacc[j], qfl[ks], bH[ki * 2], bH[ki * 2 + 1]);
                }
            }
        }

        // ---- causal mask on diagonal tile ----
        if (kt == qb) {
            const int kbase = kt * 128;
#pragma unroll
            for (int j = 0; j < 16; j++) {
                int col = kbase + j * 8 + c2;
                if (col > row_a)         sacc[j][0] = -1e30f;
                if (col + 1 > row_a)     sacc[j][1] = -1e30f;
                if (col > row_a + 8)     sacc[j][2] = -1e30f;
                if (col + 1 > row_a + 8) sacc[j][3] = -1e30f;
            }
        }

        // ---- online softmax (rows r0, r0+8; quad-reduced max) ----
        float mx0 = -1e30f, mx1 = -1e30f;
#pragma unroll
        for (int j = 0; j < 16; j++) {
            mx0 = fmaxf(mx0, fmaxf(sacc[j][0], sacc[j][1]));
            mx1 = fmaxf(mx1, fmaxf(sacc[j][2], sacc[j][3]));
        }
        mx0 = fmaxf(mx0, __shfl_xor_sync(0xffffffffu, mx0, 1));
        mx0 = fmaxf(mx0, __shfl_xor_sync(0xffffffffu, mx0, 2));
        mx1 = fmaxf(mx1, __shfl_xor_sync(0xffffffffu, mx1, 1));
        mx1 = fmaxf(mx1, __shfl_xor_sync(0xffffffffu, mx1, 2));
        float mn0 = fmaxf(m0, mx0), mn1 = fmaxf(m1, mx1);
        float a0 = __expf(m0 - mn0), a1 = __expf(m1 - mn1);
        m0 = mn0; m1 = mn1;
        float s0 = 0.f, s1 = 0.f;
#pragma unroll
        for (int j = 0; j < 16; j++) {
            sacc[j][0] = __expf(sacc[j][0] - m0);
            sacc[j][1] = __expf(sacc[j][1] - m0);
            sacc[j][2] = __expf(sacc[j][2] - m1);
            sacc[j][3] = __expf(sacc[j][3] - m1);
            s0 += sacc[j][0] + sacc[j][1];
            s1 += sacc[j][2] + sacc[j][3];
        }
        l0 = l0 * a0 + s0;     // per-thread partial; quad-reduced at the end
        l1 = l1 * a1 + s1;
#pragma unroll
        for (int jd = 0; jd < 8; jd++) {
            oacc[jd][0] *= a0; oacc[jd][1] *= a0;
            oacc[jd][2] *= a1; oacc[jd][3] *= a1;
        }

        // ---- PV: O += P V  (P hi/lo from acc frags, V^T hi/lo; 3-pass) ----
        const uint32_t vb = kb + 2 * KSTG;
#pragma unroll
        for (int koff = 0; koff < 4; koff++) {
            uint32_t pah[2][4], pal[2][4];
#pragma unroll
            for (int ki = 0; ki < 2; ki++) {
                int j0 = (koff * 2 + ki) * 2;     // acc tiles j0, j0+1
                pah[ki][0] = bf2(sacc[j0][0],     sacc[j0][1]);
                pah[ki][1] = bf2(sacc[j0][2],     sacc[j0][3]);
                pah[ki][2] = bf2(sacc[j0 + 1][0], sacc[j0 + 1][1]);
                pah[ki][3] = bf2(sacc[j0 + 1][2], sacc[j0 + 1][3]);
                pal[ki][0] = bf2(bflo(sacc[j0][0]),     bflo(sacc[j0][1]));
                pal[ki][1] = bf2(bflo(sacc[j0][2]),     bflo(sacc[j0][3]));
                pal[ki][2] = bf2(bflo(sacc[j0 + 1][0]), bflo(sacc[j0 + 1][1]));
                pal[ki][3] = bf2(bflo(sacc[j0 + 1][2]), bflo(sacc[j0 + 1][3]));
            }
#pragma unroll
            for (int jd = 0; jd < 8; jd++) {
                uint32_t rv = vb + (uint32_t)((jd * 8 + (lane & 7)) * 272 +
                                              ((lane >> 3) & 3) * 16 + koff * 64);
                uint32_t vH[4], vL[4];
                LDSM_X4(vH, rv);
                LDSM_X4(vL, rv + VSTG);
#pragma unroll
                for (int ki = 0; ki < 2; ki++) {
                    MMA16816(oacc[jd], pah[ki], vH[ki * 2], vH[ki * 2 + 1]);
                    MMA16816(oacc[jd], pah[ki], vL[ki * 2], vL[ki * 2 + 1]);
                    MMA16816(oacc[jd], pal[ki], vH[ki * 2], vH[ki * 2 + 1]);
                }
            }
        }
        __syncthreads();
    }

    // ---- epilogue: normalize, split hi/lo, store to g_yh/g_yl ----
    l0 += __shfl_xor_sync(0xffffffffu, l0, 1);
    l0 += __shfl_xor_sync(0xffffffffu, l0, 2);
    l1 += __shfl_xor_sync(0xffffffffu, l1, 1);
    l1 += __shfl_xor_sync(0xffffffffu, l1, 2);
    const float inv0 = 1.f / l0, inv1 = 1.f / l1;
    const size_t y0 = ((size_t)(b * T_) + row_a) * C_ + h * 64;
    const size_t y1 = ((size_t)(b * T_) + row_a + 8) * C_ + h * 64;
#pragma unroll
    for (int jd = 0; jd < 8; jd++) {
        int d = jd * 8 + c2;
        float v00 = oacc[jd][0] * inv0, v01 = oacc[jd][1] * inv0;
        float v10 = oacc[jd][2] * inv1, v11 = oacc[jd][3] * inv1;
        *(uint32_t*)(g_yh + y0 + d) = bf2(v00, v01);
        *(uint32_t*)(g_yl + y0 + d) = bf2(bflo(v00), bflo(v01));
        *(uint32_t*)(g_yh + y1 + d) = bf2(v10, v11);
        *(uint32_t*)(g_yl + y1 + d) = bf2(bflo(v10), bflo(v11));
    }
}

// ---------------- launch ------------------------------------------------------------
extern "C" void kernel_launch(void* const* d_in, const int* in_sizes, int n_in,
                              void* d_out, int out_size) {
    (void)in_sizes; (void)n_in; (void)out_size;
    const float* x      = (const float*)d_in[0];
    const float* W_attn = (const float*)d_in[1];
    const float* b_attn = (const float*)d_in[2];
    const float* W_proj = (const float*)d_in[3];
    const float* b_proj = (const float*)d_in[4];
    float* out = (float*)d_out;

    cudaFuncSetAttribute(attn_mma_kernel, cudaFuncAttributeMaxDynamicSharedMemorySize,
                         ATTN_SMEM);
    cudaFuncSetAttribute(tc_gemm_kernel<N1_, 1>,
                         cudaFuncAttributeMaxDynamicSharedMemorySize, GEMM_SMEM);
    cudaFuncSetAttribute(tc_gemm_kernel<C_, 0>,
                         cudaFuncAttributeMaxDynamicSharedMemorySize, GEMM_SMEM);

    rope_tables_kernel<<<(T_ * 32 + 255) / 256, 256>>>();
    convert_split_kernel<<<(M_ * C_ / 4 + 255) / 256, 256>>>(x);
    convert_wT_kernel<0><<<dim3(N1_ / 32, C_ / 32), dim3(32, 8)>>>(W_attn);
    convert_wT_kernel<1><<<dim3(C_ / 32, C_ / 32), dim3(32, 8)>>>(W_proj);

    tc_gemm_kernel<N1_, 1><<<dim3(N1_ / 128, M_ / 128), 256, GEMM_SMEM>>>(b_attn, nullptr);

    rope_apply_kernel<<<(BHD * T_ * 32 + 255) / 256, 256>>>();
    transpose_v_kernel<<<dim3(T_ / 32, D_ / 32, BHD), dim3(32, 8)>>>();

    attn_mma_kernel<<<dim3(T_ / 128, BHD), 256, ATTN_SMEM>>>();

    tc_gemm_kernel<C_, 0><<<dim3(C_ / 128, M_ / 128), 256, GEMM_SMEM>>>(b_proj, out);
}

// round 7
// speedup vs baseline: 4.8720x; 1.1357x over previous
#include <cuda_runtime.h>
#include <cuda_bf16.h>
#include <math.h>
#include <cstdint>

// Fixed problem shapes
#define B_   4
#define T_   2048
#define C_   768
#define H_   12
#define D_   64
#define M_   (B_ * T_)    // 8192
#define N1_  (3 * C_)     // 2304
#define BHD  (B_ * H_)    // 48

// ---------------- scratch (device globals; referenced ONLY in device code) --------
__device__ float g_cosT[T_ * (D_ / 2)];
__device__ float g_sinT[T_ * (D_ / 2)];

// bf16 hi/lo operand buffers
__device__ __nv_bfloat16 g_xh[M_ * C_],  g_xl[M_ * C_];      // x split
__device__ __nv_bfloat16 g_yh[M_ * C_],  g_yl[M_ * C_];      // attn out split
__device__ __nv_bfloat16 g_wah[N1_ * C_], g_wal[N1_ * C_];   // W_attn^T [N][K]
__device__ __nv_bfloat16 g_wph[C_ * C_],  g_wpl[C_ * C_];    // W_proj^T [N][K]
__device__ __nv_bfloat16 g_qh[BHD * T_ * D_], g_ql[BHD * T_ * D_];  // roped q (scaled)
__device__ __nv_bfloat16 g_kh[BHD * T_ * D_], g_kl[BHD * T_ * D_];  // roped k
__device__ __nv_bfloat16 g_vth[BHD * D_ * T_], g_vtl[BHD * D_ * T_]; // V^T [B,H,D,T]

// ---------------- helpers -----------------------------------------------------------
__device__ __forceinline__ uint32_t smem_u32(const void* p) {
    uint32_t a;
    asm("{ .reg .u64 t; cvta.to.shared.u64 t, %1; cvt.u32.u64 %0, t; }" : "=r"(a) : "l"(p));
    return a;
}
#define LDSM_X4(r, a)                                                           \
    asm volatile("ldmatrix.sync.aligned.m8n8.x4.shared.b16 {%0,%1,%2,%3},[%4];" \
        : "=r"((r)[0]), "=r"((r)[1]), "=r"((r)[2]), "=r"((r)[3]) : "r"(a))
#define MMA16816(d, a, b0, b1)                                                  \
    asm volatile("mma.sync.aligned.m16n8k16.row.col.f32.bf16.bf16.f32 "         \
        "{%0,%1,%2,%3},{%4,%5,%6,%7},{%8,%9},{%0,%1,%2,%3};"                    \
        : "+f"((d)[0]), "+f"((d)[1]), "+f"((d)[2]), "+f"((d)[3])                \
        : "r"((a)[0]), "r"((a)[1]), "r"((a)[2]), "r"((a)[3]), "r"(b0), "r"(b1))
#define CP16(dst, src) \
    asm volatile("cp.async.cg.shared.global [%0], [%1], 16;" :: "r"(dst), "l"(src))

__device__ __forceinline__ uint32_t bf2(float a, float b) {
    __nv_bfloat162 t = __floats2bfloat162_rn(a, b);
    return *(uint32_t*)&t;
}
__device__ __forceinline__ float bflo(float v) {   // residual after bf16 round
    return v - __bfloat162float(__float2bfloat16(v));
}

// ---------------- RoPE tables ------------------------------------------------------
__global__ void rope_tables_kernel() {
    int idx = blockIdx.x * blockDim.x + threadIdx.x;
    if (idx >= T_ * 32) return;
    int t = idx >> 5;
    int i = idx & 31;
    double inv = exp(-((double)i / 32.0) * log(10000.0));
    double ang = (double)t * inv;
    g_cosT[idx] = (float)cos(ang);
    g_sinT[idx] = (float)sin(ang);
}

// ---------------- fp32 -> bf16 hi/lo split of x -------------------------------------
__global__ void convert_split_kernel(const float* __restrict__ src) {
    const int n4 = M_ * C_ / 4;
    int i = blockIdx.x * blockDim.x + threadIdx.x;
    if (i >= n4) return;
    float4 v = ((const float4*)src)[i];
    float vv[4] = {v.x, v.y, v.z, v.w};
    uint32_t ph[2], pl[2];
#pragma unroll
    for (int p = 0; p < 2; p++) {
        ph[p] = bf2(vv[p * 2], vv[p * 2 + 1]);
        pl[p] = bf2(bflo(vv[p * 2]), bflo(vv[p * 2 + 1]));
    }
    ((uint2*)g_xh)[i] = make_uint2(ph[0], ph[1]);
    ((uint2*)g_xl)[i] = make_uint2(pl[0], pl[1]);
}

// ---------------- W[K][N] -> W^T[N][K] with hi/lo split -----------------------------
template <int WHICH>
__global__ void convert_wT_kernel(const float* __restrict__ W) {
    const int K = C_;
    const int N = (WHICH == 0) ? N1_ : C_;
    __nv_bfloat16* Th = (WHICH == 0) ? g_wah : g_wph;
    __nv_bfloat16* Tl = (WHICH == 0) ? g_wal : g_wpl;
    __shared__ float tile[32][33];
    int k0 = blockIdx.y * 32, n0 = blockIdx.x * 32;
    int tx = threadIdx.x, ty = threadIdx.y;
    for (int r = ty; r < 32; r += 8)
        tile[r][tx] = W[(size_t)(k0 + r) * N + n0 + tx];
    __syncthreads();
    for (int r = ty; r < 32; r += 8) {
        float v = tile[tx][r];
        size_t o = (size_t)(n0 + r) * K + k0 + tx;
        Th[o] = __float2bfloat16(v);
        Tl[o] = __float2bfloat16(bflo(v));
    }
}

// ---------------- mma.sync GEMM: D[128m,128n] = A[m,K].B^T[n,K] + bias -------------
// bf16 hi/lo 3-pass, BK=32, cp.async double buffer, 8 warps (4m x 2n), 32x64/warp.
// EPI==1 (QKV): fused epilogue — RoPE q/k (q scaled 1/8) + hi/lo split into
//               g_qh/ql/kh/kl head-major, and V transposed into g_vth/vtl.
// EPI==0 (proj): A = g_yh/g_yl, B = g_wph/g_wpl, fp32 out + bias.
#define STAGE_B   40960
#define TILE_B    10240
#define GEMM_SMEM (2 * STAGE_B)

template <int NT, int EPI>
__global__ __launch_bounds__(256, 2) void tc_gemm_kernel(
    const float* __restrict__ bias, float* __restrict__ Cout)
{
    extern __shared__ __align__(128) char smem[];
    const uint32_t sb0 = smem_u32(smem);
    const int tid  = threadIdx.x;
    const int lane = tid & 31;
    const int warp = tid >> 5;
    const int m_w  = (warp >> 1) * 32;
    const int n_w  = (warp & 1) * 64;
    const int m0 = blockIdx.y * 128;
    const int n0 = blockIdx.x * 128;

    const __nv_bfloat16* srcs[4];
    if (EPI == 1) { srcs[0] = g_xh; srcs[1] = g_xl; srcs[2] = g_wah; srcs[3] = g_wal; }
    else          { srcs[0] = g_yh; srcs[1] = g_yl; srcs[2] = g_wph; srcs[3] = g_wpl; }

    auto load_chunk = [&](int kc, int st) {
        const uint32_t sbase = sb0 + (uint32_t)st * STAGE_B;
        const int k0 = kc * 32;
#pragma unroll
        for (int it = 0; it < 8; ++it) {
            int idx  = it * 256 + tid;
            int tile = idx >> 9;
            int r    = (idx >> 2) & 127;
            int seg  = idx & 3;
            int rowbase = ((tile < 2) ? m0 : n0) + r;
            const void* g = srcs[tile] + (size_t)rowbase * C_ + k0 + seg * 8;
            uint32_t dst = sbase + (uint32_t)tile * TILE_B + (uint32_t)(r * 80 + seg * 16);
            CP16(dst, g);
        }
        asm volatile("cp.async.commit_group;" ::: "memory");
    };

    float acc[2][8][4];
#pragma unroll
    for (int i = 0; i < 2; i++)
#pragma unroll
        for (int j = 0; j < 8; j++)
#pragma unroll
            for (int r = 0; r < 4; r++) acc[i][j][r] = 0.f;

    load_chunk(0, 0);
    const int NCHUNK = C_ / 32;
    for (int c = 0; c < NCHUNK; ++c) {
        const int st = c & 1;
        if (c + 1 < NCHUNK) {
            load_chunk(c + 1, st ^ 1);
            asm volatile("cp.async.wait_group 1;" ::: "memory");
        } else {
            asm volatile("cp.async.wait_group 0;" ::: "memory");
        }
        __syncthreads();

        const uint32_t sA_h = sb0 + (uint32_t)st * STAGE_B;
        const uint32_t sA_l = sA_h + TILE_B;
        const uint32_t sB_h = sA_h + 2 * TILE_B;
        const uint32_t sB_l = sA_h + 3 * TILE_B;

        uint32_t aH[2][2][4], aL[2][2][4];
#pragma unroll
        for (int ks = 0; ks < 2; ks++)
#pragma unroll
            for (int i = 0; i < 2; i++) {
                uint32_t ra = (uint32_t)((m_w + i * 16 + (lane & 15)) * 80 +
                                         ks * 32 + ((lane >> 4) & 1) * 16);
                LDSM_X4(aH[ks][i], sA_h + ra);
                LDSM_X4(aL[ks][i], sA_l + ra);
            }
#pragma unroll
        for (int j = 0; j < 8; j++) {
            uint32_t rb = (uint32_t)((n_w + j * 8 + (lane & 7)) * 80 +
                                     ((lane >> 3) & 3) * 16);
            uint32_t bH[4], bL[4];
            LDSM_X4(bH, sB_h + rb);
            LDSM_X4(bL, sB_l + rb);
#pragma unroll
            for (int ks = 0; ks < 2; ks++)
#pragma unroll
                for (int i = 0; i < 2; i++) {
                    MMA16816(acc[i][j], aH[ks][i], bH[ks * 2], bH[ks * 2 + 1]);
                    MMA16816(acc[i][j], aH[ks][i], bL[ks * 2], bL[ks * 2 + 1]);
                    MMA16816(acc[i][j], aL[ks][i], bH[ks * 2], bH[ks * 2 + 1]);
                }
        }
        __syncthreads();
    }

    // ---- stage results (bias added) into smem ----
    float* stg = (float*)smem;   // 128 x 132
#pragma unroll
    for (int i = 0; i < 2; i++) {
        int row = m_w + i * 16 + (lane >> 2);
#pragma unroll
        for (int j = 0; j < 8; j++) {
            int col = n_w + j * 8 + (lane & 3) * 2;
            float b0 = bias[n0 + col], b1 = bias[n0 + col + 1];
            stg[row * 132 + col]           = acc[i][j][0] + b0;
            stg[row * 132 + col + 1]       = acc[i][j][1] + b1;
            stg[(row + 8) * 132 + col]     = acc[i][j][2] + b0;
            stg[(row + 8) * 132 + col + 1] = acc[i][j][3] + b1;
        }
    }
    __syncthreads();

    if (EPI == 0) {
#pragma unroll
        for (int it = 0; it < 16; ++it) {
            int idx = it * 256 + tid;
            int ml = idx >> 5;
            int c4 = (idx & 31) * 4;
            float4 v = *(const float4*)(stg + ml * 132 + c4);
            *(float4*)(Cout + (size_t)(m0 + ml) * NT + n0 + c4) = v;
        }
    } else {
        const int which = n0 / C_;               // 0=q 1=k 2=v (tile never spans)
        const int hbase = (n0 % C_) / 64;        // tile covers heads hbase, hbase+1
        const int bb = m0 >> 11;                 // batch (constant per CTA)
        const int t0 = m0 & (T_ - 1);
        if (which < 2) {
            __nv_bfloat16* dh = which ? g_kh : g_qh;
            __nv_bfloat16* dl = which ? g_kl : g_ql;
            const float sc = which ? 1.0f : 0.125f;
            // 128 m x 2 heads x 16 d-pairs
#pragma unroll
            for (int it = 0; it < 16; ++it) {
                int idx = it * 256 + tid;
                int ml = idx >> 5;
                int hl = (idx >> 4) & 1;
                int d  = (idx & 15) * 2;         // even, < 32
                int t  = t0 + ml;
                float c0 = g_cosT[(t << 5) + d],     s0 = g_sinT[(t << 5) + d];
                float c1 = g_cosT[(t << 5) + d + 1], s1 = g_sinT[(t << 5) + d + 1];
                const float* row = stg + ml * 132 + hl * 64 + d;
                float x1a = row[0],  x1b = row[1];
                float x2a = row[32], x2b = row[33];
                float y1a = (x1a * c0 + x2a * s0) * sc;
                float y1b = (x1b * c1 + x2b * s1) * sc;
                float y2a = (-x1a * s0 + x2a * c0) * sc;
                float y2b = (-x1b * s1 + x2b * c1) * sc;
                size_t o = ((size_t)(bb * H_ + hbase + hl) * T_ + t) * 64 + d;
                *(uint32_t*)(dh + o)      = bf2(y1a, y1b);
                *(uint32_t*)(dl + o)      = bf2(bflo(y1a), bflo(y1b));
                *(uint32_t*)(dh + o + 32) = bf2(y2a, y2b);
                *(uint32_t*)(dl + o + 32) = bf2(bflo(y2a), bflo(y2b));
            }
        } else {
            // V: transpose into g_vth/g_vtl [bh][d][t]
#pragma unroll
            for (int it = 0; it < 32; ++it) {
                int idx  = it * 256 + tid;
                int dcol = idx >> 6;             // 0..127
                int tp   = (idx & 63) * 2;       // 0..126
                int hl = dcol >> 6;
                int dd = dcol & 63;
                float v0 = stg[tp * 132 + dcol];
                float v1 = stg[(tp + 1) * 132 + dcol];
                size_t o = ((size_t)(bb * H_ + hbase + hl) * 64 + dd) * T_ + t0 + tp;
                *(uint32_t*)(g_vth + o) = bf2(v0, v1);
                *(uint32_t*)(g_vtl + o) = bf2(bflo(v0), bflo(v1));
            }
        }
    }
}

// ---------------- Tensor-core flash attention (unchanged from round 6) -------------
#define KSTG 18432                      // 128 rows * 144B
#define VSTG 17408                      // 64 rows * 272B
#define STG_BYTES (2 * KSTG + 2 * VSTG) // 71680
#define ATTN_SMEM (2 * STG_BYTES)       // 143360

__global__ __launch_bounds__(256, 1) void attn_mma_kernel() {
    extern __shared__ __align__(128) char sm[];
    const uint32_t sb = smem_u32(sm);
    const int tid  = threadIdx.x;
    const int lane = tid & 31;
    const int w    = tid >> 5;
    const int bh   = blockIdx.y;
    const int qb   = (int)gridDim.x - 1 - (int)blockIdx.x;
    const int b    = bh / H_;
    const int h    = bh - b * H_;
    const size_t hb = (size_t)bh * T_ * D_;
    const int qbase = qb * 128;
    const int r0 = lane >> 2;
    const int c2 = (lane & 3) * 2;
    const int row_a = qbase + w * 16 + r0;

    uint32_t qfh[4][4], qfl[4][4];
#pragma unroll
    for (int ks = 0; ks < 4; ks++) {
        int d = ks * 16 + c2;
        size_t o0 = hb + (size_t)row_a * 64 + d;
        size_t o1 = hb + (size_t)(row_a + 8) * 64 + d;
        qfh[ks][0] = *(const uint32_t*)(g_qh + o0);
        qfh[ks][1] = *(const uint32_t*)(g_qh + o1);
        qfh[ks][2] = *(const uint32_t*)(g_qh + o0 + 8);
        qfh[ks][3] = *(const uint32_t*)(g_qh + o1 + 8);
        qfl[ks][0] = *(const uint32_t*)(g_ql + o0);
        qfl[ks][1] = *(const uint32_t*)(g_ql + o1);
        qfl[ks][2] = *(const uint32_t*)(g_ql + o0 + 8);
        qfl[ks][3] = *(const uint32_t*)(g_ql + o1 + 8);
    }

    const __nv_bfloat16* kh = g_kh + hb;
    const __nv_bfloat16* kl = g_kl + hb;
    const __nv_bfloat16* vh = g_vth + hb;
    const __nv_bfloat16* vl = g_vtl + hb;

    auto load_stage = [&](int kt, int st) {
        const uint32_t sbase = sb + (uint32_t)st * STG_BYTES;
        const int kbase = kt * 128;
#pragma unroll
        for (int it = 0; it < 8; ++it) {
            int idx = it * 256 + tid;
            int tile = idx >> 10;
            int r    = (idx >> 3) & 127;
            int seg  = idx & 7;
            const void* g = (tile ? kl : kh) + (size_t)(kbase + r) * 64 + seg * 8;
            CP16(sbase + (uint32_t)(tile * KSTG + r * 144 + seg * 16), g);
        }
#pragma unroll
        for (int it = 0; it < 8; ++it) {
            int idx = it * 256 + tid;
            int tile = idx >> 10;
            int r    = (idx >> 4) & 63;
            int seg  = idx & 15;
            const void* g = (tile ? vl : vh) + (size_t)r * T_ + kbase + seg * 8;
            CP16(sbase + (uint32_t)(2 * KSTG + tile * VSTG + r * 272 + seg * 16), g);
        }
        asm volatile("cp.async.commit_group;" ::: "memory");
    };

    float oacc[8][4];
#pragma unroll
    for (int jd = 0; jd < 8; jd++)
#pragma unroll
        for (int e = 0; e < 4; e++) oacc[jd][e] = 0.f;
    float m0 = -1e30f, m1 = -1e30f, l0 = 0.f, l1 = 0.f;

    load_stage(0, 0);

    for (int kt = 0; kt <= qb; kt++) {
        const int st = kt & 1;
        if (kt < qb) {
            load_stage(kt + 1, st ^ 1);
            asm volatile("cp.async.wait_group 1;" ::: "memory");
        } else {
            asm volatile("cp.async.wait_group 0;" ::: "memory");
        }
        __syncthreads();

        const uint32_t kb = sb + (uint32_t)st * STG_BYTES;

        float sacc[16][4];
#pragma unroll
        for (int j = 0; j < 16; j++)
#pragma unroll
            for (int e = 0; e < 4; e++) sacc[j][e] = 0.f;

#pragma unroll
        for (int j = 0; j < 16; j++) {
            uint32_t rbase = kb + (uint32_t)((j * 8 + (lane & 7)) * 144 +
                                             ((lane >> 3) & 3) * 16);
#pragma unroll
            for (int half = 0; half < 2; half++) {
                uint32_t bH[4], bL[4];
                LDSM_X4(bH, rbase + half * 64);
                LDSM_X4(bL, rbase + KSTG + half * 64);
#pragma unroll
                for (int ki = 0; ki < 2; ki++) {
                    int ks = half * 2 + ki;
                    MMA16816(sacc[j], qfh[ks], bH[ki * 2], bH[ki * 2 + 1]);
                    MMA16816(sacc[j], qfh[ks], bL[ki * 2], bL[ki * 2 + 1]);
                    MMA16816(sacc[j], qfl[ks], bH[ki * 2], bH[ki * 2 + 1]);
                }
            }
        }

        if (kt == qb) {
            const int kbase = kt * 128;
#pragma unroll
            for (int j = 0; j < 16; j++) {
                int col = kbase + j * 8 + c2;
                if (col > row_a)         sacc[j][0] = -1e30f;
                if (col + 1 > row_a)     sacc[j][1] = -1e30f;
                if (col > row_a + 8)     sacc[j][2] = -1e30f;
                if (col + 1 > row_a + 8) sacc[j][3] = -1e30f;
            }
        }

        float mx0 = -1e30f, mx1 = -1e30f;
#pragma unroll
        for (int j = 0; j < 16; j++) {
            mx0 = fmaxf(mx0, fmaxf(sacc[j][0], sacc[j][1]));
            mx1 = fmaxf(mx1, fmaxf(sacc[j][2], sacc[j][3]));
        }
        mx0 = fmaxf(mx0, __shfl_xor_sync(0xffffffffu, mx0, 1));
        mx0 = fmaxf(mx0, __shfl_xor_sync(0xffffffffu, mx0, 2));
        mx1 = fmaxf(mx1, __shfl_xor_sync(0xffffffffu, mx1, 1));
        mx1 = fmaxf(mx1, __shfl_xor_sync(0xffffffffu, mx1, 2));
        float mn0 = fmaxf(m0, mx0), mn1 = fmaxf(m1, mx1);
        float a0 = __expf(m0 - mn0), a1 = __expf(m1 - mn1);
        m0 = mn0; m1 = mn1;
        float s0 = 0.f, s1 = 0.f;
#pragma unroll
        for (int j = 0; j < 16; j++) {
            sacc[j][0] = __expf(sacc[j][0] - m0);
            sacc[j][1] = __expf(sacc[j][1] - m0);
            sacc[j][2] = __expf(sacc[j][2] - m1);
            sacc[j][3] = __expf(sacc[j][3] - m1);
            s0 += sacc[j][0] + sacc[j][1];
            s1 += sacc[j][2] + sacc[j][3];
        }
        l0 = l0 * a0 + s0;
        l1 = l1 * a1 + s1;
#pragma unroll
        for (int jd = 0; jd < 8; jd++) {
            oacc[jd][0] *= a0; oacc[jd][1] *= a0;
            oacc[jd][2] *= a1; oacc[jd][3] *= a1;
        }

        const uint32_t vb = kb + 2 * KSTG;
#pragma unroll
        for (int koff = 0; koff < 4; koff++) {
            uint32_t pah[2][4], pal[2][4];
#pragma unroll
            for (int ki = 0; ki < 2; ki++) {
                int j0 = (koff * 2 + ki) * 2;
                pah[ki][0] = bf2(sacc[j0][0],     sacc[j0][1]);
                pah[ki][1] = bf2(sacc[j0][2],     sacc[j0][3]);
                pah[ki][2] = bf2(sacc[j0 + 1][0], sacc[j0 + 1][1]);
                pah[ki][3] = bf2(sacc[j0 + 1][2], sacc[j0 + 1][3]);
                pal[ki][0] = bf2(bflo(sacc[j0][0]),     bflo(sacc[j0][1]));
                pal[ki][1] = bf2(bflo(sacc[j0][2]),     bflo(sacc[j0][3]));
                pal[ki][2] = bf2(bflo(sacc[j0 + 1][0]), bflo(sacc[j0 + 1][1]));
                pal[ki][3] = bf2(bflo(sacc[j0 + 1][2]), bflo(sacc[j0 + 1][3]));
            }
#pragma unroll
            for (int jd = 0; jd < 8; jd++) {
                uint32_t rv = vb + (uint32_t)((jd * 8 + (lane & 7)) * 272 +
                                              ((lane >> 3) & 3) * 16 + koff * 64);
                uint32_t vH[4], vL[4];
                LDSM_X4(vH, rv);
                LDSM_X4(vL, rv + VSTG);
#pragma unroll
                for (int ki = 0; ki < 2; ki++) {
                    MMA16816(oacc[jd], pah[ki], vH[ki * 2], vH[ki * 2 + 1]);
                    MMA16816(oacc[jd], pah[ki], vL[ki * 2], vL[ki * 2 + 1]);
                    MMA16816(oacc[jd], pal[ki], vH[ki * 2], vH[ki * 2 + 1]);
                }
            }
        }
        __syncthreads();
    }

    l0 += __shfl_xor_sync(0xffffffffu, l0, 1);
    l0 += __shfl_xor_sync(0xffffffffu, l0, 2);
    l1 += __shfl_xor_sync(0xffffffffu, l1, 1);
    l1 += __shfl_xor_sync(0xffffffffu, l1, 2);
    const float inv0 = 1.f / l0, inv1 = 1.f / l1;
    const size_t y0 = ((size_t)(b * T_) + row_a) * C_ + h * 64;
    const size_t y1 = ((size_t)(b * T_) + row_a + 8) * C_ + h * 64;
#pragma unroll
    for (int jd = 0; jd < 8; jd++) {
        int d = jd * 8 + c2;
        float v00 = oacc[jd][0] * inv0, v01 = oacc[jd][1] * inv0;
        float v10 = oacc[jd][2] * inv1, v11 = oacc[jd][3] * inv1;
        *(uint32_t*)(g_yh + y0 + d) = bf2(v00, v01);
        *(uint32_t*)(g_yl + y0 + d) = bf2(bflo(v00), bflo(v01));
        *(uint32_t*)(g_yh + y1 + d) = bf2(v10, v11);
        *(uint32_t*)(g_yl + y1 + d) = bf2(bflo(v10), bflo(v11));
    }
}

// ---------------- launch ------------------------------------------------------------
extern "C" void kernel_launch(void* const* d_in, const int* in_sizes, int n_in,
                              void* d_out, int out_size) {
    (void)in_sizes; (void)n_in; (void)out_size;
    const float* x      = (const float*)d_in[0];
    const float* W_attn = (const float*)d_in[1];
    const float* b_attn = (const float*)d_in[2];
    const float* W_proj = (const float*)d_in[3];
    const float* b_proj = (const float*)d_in[4];
    float* out = (float*)d_out;

    cudaFuncSetAttribute(attn_mma_kernel, cudaFuncAttributeMaxDynamicSharedMemorySize,
                         ATTN_SMEM);
    cudaFuncSetAttribute(tc_gemm_kernel<N1_, 1>,
                         cudaFuncAttributeMaxDynamicSharedMemorySize, GEMM_SMEM);
    cudaFuncSetAttribute(tc_gemm_kernel<C_, 0>,
                         cudaFuncAttributeMaxDynamicSharedMemorySize, GEMM_SMEM);

    rope_tables_kernel<<<(T_ * 32 + 255) / 256, 256>>>();
    convert_split_kernel<<<(M_ * C_ / 4 + 255) / 256, 256>>>(x);
    convert_wT_kernel<0><<<dim3(N1_ / 32, C_ / 32), dim3(32, 8)>>>(W_attn);
    convert_wT_kernel<1><<<dim3(C_ / 32, C_ / 32), dim3(32, 8)>>>(W_proj);

    tc_gemm_kernel<N1_, 1><<<dim3(N1_ / 128, M_ / 128), 256, GEMM_SMEM>>>(b_attn, nullptr);

    attn_mma_kernel<<<dim3(T_ / 128, BHD), 256, ATTN_SMEM>>>();

    tc_gemm_kernel<C_, 0><<<dim3(C_ / 128, M_ / 128), 256, GEMM_SMEM>>>(b_proj, out);
}